// round 6
// baseline (speedup 1.0000x reference)
#include <cuda_runtime.h>
#include <math.h>

#define N       8192
#define FIXP    4194304.0f      // 2^22 fixed point for last-row stats
#define QB      64
#define QT      128

// ---- device globals -------------------------------------------------------
__device__ float         g_x[N];
__device__ unsigned char g_lab[N];
__device__ double        g_Ad[N], g_Bd[N];       // exp(+-16x), double
__device__ int           g_cnt[10];
__device__ int           g_off[11];
__device__ float         g_mn[10], g_mx[10];
__device__ float         g_xs[N];                // sorted by (label, x, idx)
__device__ double        g_As[N], g_Bs[N];
__device__ double        g_PA[N + 16];           // per-label EXCLUSIVE prefix of A
__device__ double        g_SB[N + 16];           // per-label SUFFIX sums of B
__device__ float         g_pls[QB];
__device__ int           g_ppc[QB];
__device__ unsigned long long g_ps = 0ull, g_ns = 0ull;
__device__ unsigned g_pc = 0u, g_nc = 0u;
__device__ unsigned g_ticket = 0u;

__device__ __forceinline__ unsigned fenc(float f) {    // order-preserving key
    unsigned u = __float_as_uint(f);
    return (u & 0x80000000u) ? ~u : (u | 0x80000000u);
}

// ---------------------------------------------------------------------------
// K1 prep (32 x 256): dtype-layout detect (JAX demotes int64->int32; odd words
// of first 16KB zero iff true int64), decode, double exp tables, label
// histogram, last-row stats (deterministic fixed-point atomics).
// ---------------------------------------------------------------------------
__global__ void __launch_bounds__(256) prep_kernel(const float* __restrict__ x,
                                                   const int* __restrict__ t32) {
    __shared__ int flag;
    __shared__ unsigned long long rps[8], rns[8];
    __shared__ int rpc[8], rnc[8];
    const int tid = threadIdx.x;
    if (tid == 0) flag = 0;
    __syncthreads();
    for (int k = tid; k < 2048; k += 256)
        if (t32[2 * k + 1] != 0) atomicOr(&flag, 1);
    __syncthreads();
    const int is32 = flag;

    const int i = blockIdx.x * 256 + tid;
    const float xi = x[i];
    const int lbl = is32 ? t32[i] : t32[2 * i];
    g_x[i] = xi;
    g_lab[i] = (unsigned char)lbl;
    const double xd = (double)xi;
    g_Ad[i] = exp(16.0 * xd);
    g_Bd[i] = exp(-16.0 * xd);
    atomicAdd(&g_cnt[lbl], 1);

    // last-row stats (fixed point, deterministic)
    const float xl = x[N - 1];
    const int   ll = is32 ? t32[N - 1] : t32[2 * (N - 1)];
    float d = fabsf(xl - xi);
    unsigned long long pq = 0ull, nq = 0ull; int pc = 0, nc = 0;
    if (lbl == ll) { if (d < 1.0f) { pq = (unsigned long long)(d * FIXP + 0.5f); pc = 1; } }
    else           { nq = (unsigned long long)(d * FIXP + 0.5f); nc = 1; }
#pragma unroll
    for (int o = 16; o; o >>= 1) {
        pq += __shfl_xor_sync(~0u, pq, o); nq += __shfl_xor_sync(~0u, nq, o);
        pc += __shfl_xor_sync(~0u, pc, o); nc += __shfl_xor_sync(~0u, nc, o);
    }
    const int w = tid >> 5, l = tid & 31;
    if (l == 0) { rps[w] = pq; rns[w] = nq; rpc[w] = pc; rnc[w] = nc; }
    __syncthreads();
    if (tid == 0) {
        unsigned long long sp = 0ull, sn = 0ull; int cp = 0, cn = 0;
        for (int k = 0; k < 8; k++) { sp += rps[k]; sn += rns[k]; cp += rpc[k]; cn += rnc[k]; }
        atomicAdd(&g_ps, sp); atomicAdd(&g_ns, sn);
        atomicAdd(&g_pc, (unsigned)cp); atomicAdd(&g_nc, (unsigned)cn);
    }
}

// ---------------------------------------------------------------------------
// K2 rank+scatter (128 x 256, 64KB smem): compound key (label, x, idx) rank by
// counting; rank == position in concatenated per-label sorted arrays.
// ---------------------------------------------------------------------------
__global__ void __launch_bounds__(256) rank_kernel() {
    extern __shared__ unsigned long long sk[];
    const int tid = threadIdx.x;
    for (int k = tid; k < N; k += 256)
        sk[k] = ((unsigned long long)g_lab[k] << 45)
              | ((unsigned long long)fenc(g_x[k]) << 13)
              | (unsigned)k;
    __syncthreads();

    const int warp = tid >> 5, lane = tid & 31;
    const int row0 = (blockIdx.x * 8 + warp) * 8;
    unsigned long long mykey[8];
    int cnt[8];
#pragma unroll
    for (int r = 0; r < 8; r++) { mykey[r] = sk[row0 + r]; cnt[r] = 0; }

    for (int j = lane; j < N; j += 32) {
        const unsigned long long kj = sk[j];
#pragma unroll
        for (int r = 0; r < 8; r++) cnt[r] += (kj < mykey[r]) ? 1 : 0;
    }
#pragma unroll
    for (int r = 0; r < 8; r++)
#pragma unroll
        for (int o = 16; o; o >>= 1)
            cnt[r] += __shfl_xor_sync(0xffffffffu, cnt[r], o);

    if (lane < 8) {
        int gr = 0;
#pragma unroll
        for (int r = 0; r < 8; r++) if (lane == r) gr = cnt[r];
        const int row = row0 + lane;
        g_xs[gr] = g_x[row];
        g_As[gr] = g_Ad[row];
        g_Bs[gr] = g_Bd[row];
    }
}

// ---------------------------------------------------------------------------
// K3 build (1 x 1024): offsets, per-label min/max, per-label EXCLUSIVE PREFIX
// of A (ascending terms -> window [aa,m) diffs accurate) and per-label SUFFIX
// sums of B (accumulated small->large; window [m,bb) = SB[m]-SB[bb] accurate).
// ---------------------------------------------------------------------------
__global__ void __launch_bounds__(1024, 1) build_kernel() {
    __shared__ int s_off[11], s_cnt[10];
    const int tid = threadIdx.x;
    if (tid == 0) {
        int acc = 0;
        for (int c = 0; c < 10; c++) {
            s_off[c] = acc; g_off[c] = acc;
            int cc = g_cnt[c]; s_cnt[c] = cc; acc += cc;
        }
        s_off[10] = acc; g_off[10] = acc;
        for (int c = 0; c < 10; c++) {
            if (s_cnt[c] > 0) {
                g_mn[c] = g_xs[s_off[c]];
                g_mx[c] = g_xs[s_off[c] + s_cnt[c] - 1];
            }
        }
    }
    __syncthreads();
    const int w = tid >> 5, lane = tid & 31;
    if (w < 20) {
        const int c = w >> 1;
        const int off = s_off[c], L = s_cnt[c];
        const int base = off + c;                       // per-label extra slot
        const int chunk = (L + 31) >> 5;
        int st = lane * chunk; if (st > L) st = L;
        int en = st + chunk;   if (en > L) en = L;

        if ((w & 1) == 0) {
            // A: forward exclusive prefix
            double s = 0.0;
            for (int k = st; k < en; k++) s += g_As[off + k];
            double t = s;
#pragma unroll
            for (int o = 1; o < 32; o <<= 1) {
                double v = __shfl_up_sync(~0u, t, o);
                if (lane >= o) t += v;
            }
            double run = t - s;
            for (int k = st; k < en; k++) { g_PA[base + k] = run; run += g_As[off + k]; }
            if (lane == 31) g_PA[base + L] = run;
        } else {
            // B: suffix sums via reversed inclusive scan (r-index = L-1-k)
            double s = 0.0;
            for (int r = st; r < en; r++) s += g_Bs[off + (L - 1 - r)];
            double t = s;
#pragma unroll
            for (int o = 1; o < 32; o <<= 1) {
                double v = __shfl_up_sync(~0u, t, o);
                if (lane >= o) t += v;
            }
            double run = t - s;
            for (int r = st; r < en; r++) {
                run += g_Bs[off + (L - 1 - r)];
                g_SB[base + (L - 1 - r)] = run;          // SB[k] = sum_{j>=k}
            }
            if (lane == 0) g_SB[base + L] = 0.0;
        }
    }
}

// ---------------------------------------------------------------------------
// K4 query (64 x 128): per row, 14-step binary searches using the EXACT fp32
// predicate fabsf(xi - xs[k]) < bound (bit-identical to reference membership),
// PA/SB prefix-difference sums, fused finalize via ticket.
// ---------------------------------------------------------------------------
__global__ void __launch_bounds__(QT) query_kernel(float* __restrict__ out) {
    __shared__ int   s_off[10], s_cnt[10];
    __shared__ float s_mn[10], s_mx[10];
    __shared__ float rls[4]; __shared__ int rpcs[4];
    __shared__ unsigned lastS;
    const int tid = threadIdx.x;
    if (tid < 10) {
        s_off[tid] = g_off[tid]; s_cnt[tid] = g_cnt[tid];
        s_mn[tid] = g_mn[tid];   s_mx[tid] = g_mx[tid];
    }
    __syncthreads();

    const int i = blockIdx.x * QT + tid;
    const float xi = g_x[i];
    const int lab = g_lab[i];
    const double Ai = g_Ad[i], Bi = g_Bd[i];

    // phase A: per-label split m_c = first r with xs > xi (10-way interleaved)
    int m[10];
    {
        int lo[10], hi[10];
#pragma unroll
        for (int c = 0; c < 10; c++) { lo[c] = 0; hi[c] = s_cnt[c]; }
        for (int s = 0; s < 14; s++) {
#pragma unroll
            for (int c = 0; c < 10; c++) {
                if (lo[c] < hi[c]) {
                    int mid = (lo[c] + hi[c]) >> 1;
                    if (g_xs[s_off[c] + mid] > xi) hi[c] = mid; else lo[c] = mid + 1;
                }
            }
        }
#pragma unroll
        for (int c = 0; c < 10; c++) m[c] = lo[c];
    }

    // phase B: threshold = max(neg extremes, own-label d<1 window endpoints)
    float th;
    {
        const int offl = s_off[lab], ml = m[lab], cl = s_cnt[lab];
        int lo = 0, hi = ml;
        for (int s = 0; s < 14; s++) {
            if (lo < hi) { int mid = (lo + hi) >> 1;
                if (fabsf(xi - g_xs[offl + mid]) < 1.0f) hi = mid; else lo = mid + 1; }
        }
        const int a0 = lo;                // a0 < ml always (self has d=0)
        lo = ml; hi = cl;
        for (int s = 0; s < 14; s++) {
            if (lo < hi) { int mid = (lo + hi) >> 1;
                if (fabsf(xi - g_xs[offl + mid]) < 1.0f) lo = mid + 1; else hi = mid; }
        }
        const int b0 = lo;
        th = fabsf(xi - g_xs[offl + a0]);
        if (b0 > ml) th = fmaxf(th, fabsf(xi - g_xs[offl + b0 - 1]));
#pragma unroll
        for (int c = 0; c < 10; c++)
            if (c != lab && s_cnt[c] > 0)
                th = fmaxf(th, fmaxf(fabsf(xi - s_mn[c]), fabsf(xi - s_mx[c])));
    }

    float loss = 0.f;
    if (th > 0.f) {
        const float pm = fminf(1.0f, th);    // pos bound: d<1 AND d<th
        int aa[10], bb[10];
        {
            int lo[10], hi[10];
#pragma unroll
            for (int c = 0; c < 10; c++) { lo[c] = 0; hi[c] = m[c]; }
            for (int s = 0; s < 14; s++) {
#pragma unroll
                for (int c = 0; c < 10; c++) {
                    const float bd = (c == lab) ? pm : th;
                    if (lo[c] < hi[c]) {
                        int mid = (lo[c] + hi[c]) >> 1;
                        if (fabsf(xi - g_xs[s_off[c] + mid]) < bd) hi[c] = mid;
                        else lo[c] = mid + 1;
                    }
                }
            }
#pragma unroll
            for (int c = 0; c < 10; c++) aa[c] = lo[c];
#pragma unroll
            for (int c = 0; c < 10; c++) { lo[c] = m[c]; hi[c] = s_cnt[c]; }
            for (int s = 0; s < 14; s++) {
#pragma unroll
                for (int c = 0; c < 10; c++) {
                    const float bd = (c == lab) ? pm : th;
                    if (lo[c] < hi[c]) {
                        int mid = (lo[c] + hi[c]) >> 1;
                        if (fabsf(xi - g_xs[s_off[c] + mid]) < bd) lo[c] = mid + 1;
                        else hi[c] = mid;
                    }
                }
            }
#pragma unroll
            for (int c = 0; c < 10; c++) bb[c] = lo[c];
        }
        // e = Bi*Aj (j left of split, window [aa,m)) + Ai*Bj (right, [m,bb))
        double pos = 0.0, neg = 0.0;
#pragma unroll
        for (int c = 0; c < 10; c++) {
            const int e = s_off[c] + c;
            const double v = Bi * (g_PA[e + m[c]] - g_PA[e + aa[c]])
                           + Ai * (g_SB[e + m[c]] - g_SB[e + bb[c]]);
            if (c == lab) pos = v; else neg += v;
        }
        // diagnostic guard: pos must be > 0 (self term ~ 1). If not, emit 0
        // so a residual bug shows as finite rel_err, not NaN.
        if (pos > 0.0) loss = (float)log((pos + fmax(neg, 0.0)) / pos);
    }

    // fused finalize
    float s = loss; int pc = (loss < 0.6f) ? 1 : 0;
#pragma unroll
    for (int o = 16; o; o >>= 1) {
        s  += __shfl_xor_sync(~0u, s, o);
        pc += __shfl_xor_sync(~0u, pc, o);
    }
    const int w = tid >> 5, lane = tid & 31;
    if (lane == 0) { rls[w] = s; rpcs[w] = pc; }
    __syncthreads();
    if (tid == 0) {
        g_pls[blockIdx.x] = rls[0] + rls[1] + rls[2] + rls[3];
        g_ppc[blockIdx.x] = rpcs[0] + rpcs[1] + rpcs[2] + rpcs[3];
        __threadfence();
        lastS = atomicAdd(&g_ticket, 1u);
    }
    __syncthreads();
    if (lastS == QB - 1) {
        __threadfence();
        if (tid < QB) {
            float v = g_pls[tid]; int c = g_ppc[tid];
#pragma unroll
            for (int o = 16; o; o >>= 1) {
                v += __shfl_xor_sync(~0u, v, o);
                c += __shfl_xor_sync(~0u, c, o);
            }
            if (tid == 0)  { rls[0] = v; rpcs[0] = c; }
            if (tid == 32) { rls[1] = v; rpcs[1] = c; }
        }
        __syncthreads();
        if (tid == 0) {
            out[0] = (rls[0] + rls[1]) / (float)N;
            out[1] = (float)(rpcs[0] + rpcs[1]) / (float)N;
            out[2] = ((float)g_ps / FIXP) / (float)g_pc;
            out[3] = ((float)g_ns / FIXP) / (float)g_nc;
            for (int c = 0; c < 10; c++) g_cnt[c] = 0;   // reset for replay
            g_ps = 0ull; g_ns = 0ull; g_pc = 0u; g_nc = 0u;
            g_ticket = 0u;
        }
    }
}

// ---------------------------------------------------------------------------
extern "C" void kernel_launch(void* const* d_in, const int* in_sizes, int n_in,
                              void* d_out, int out_size) {
    const float* x   = (const float*)d_in[0];
    const int*   t32 = (const int*)d_in[1];
    float*       out = (float*)d_out;

    cudaFuncSetAttribute(rank_kernel,
                         cudaFuncAttributeMaxDynamicSharedMemorySize, 65536);

    prep_kernel<<<32, 256>>>(x, t32);
    rank_kernel<<<128, 256, 65536>>>();
    build_kernel<<<1, 1024>>>();
    query_kernel<<<QB, QT>>>(out);
}

// round 7
// speedup vs baseline: 1.1540x; 1.1540x over previous
#include <cuda_runtime.h>
#include <math.h>

#define N       8192
#define FIXP    4194304.0f      // 2^22 fixed point for last-row stats
#define QB      64
#define QT      128

// ---- device globals -------------------------------------------------------
__device__ float         g_x[N];
__device__ unsigned char g_lab[N];
__device__ double        g_Ad[N], g_Bd[N];       // exp(+-16x), double
__device__ int           g_cnt[10];
__device__ int           g_off[11];
__device__ float         g_mn[10], g_mx[10];
__device__ float         g_xs[N];                // sorted by (label, x, idx)
__device__ double        g_As[N], g_Bs[N];
__device__ double        g_PA[N + 16];           // per-label EXCLUSIVE prefix of A
__device__ double        g_SB[N + 16];           // per-label SUFFIX sums of B
__device__ float         g_pls[QB];
__device__ int           g_ppc[QB];
__device__ unsigned long long g_ps = 0ull, g_ns = 0ull;
__device__ unsigned g_pc = 0u, g_nc = 0u;
__device__ unsigned g_ticket = 0u;

__device__ __forceinline__ unsigned fenc(float f) {    // order-preserving key
    unsigned u = __float_as_uint(f);
    return (u & 0x80000000u) ? ~u : (u | 0x80000000u);
}

// ---------------------------------------------------------------------------
// K1 prep (32 x 256): dtype-layout detect (JAX demotes int64->int32; odd words
// of first 16KB zero iff true int64), decode, double exp tables, label
// histogram, last-row stats (deterministic fixed-point atomics).
// ---------------------------------------------------------------------------
__global__ void __launch_bounds__(256) prep_kernel(const float* __restrict__ x,
                                                   const int* __restrict__ t32) {
    __shared__ int flag;
    __shared__ unsigned long long rps[8], rns[8];
    __shared__ int rpc[8], rnc[8];
    const int tid = threadIdx.x;
    if (tid == 0) flag = 0;
    __syncthreads();
    for (int k = tid; k < 2048; k += 256)
        if (t32[2 * k + 1] != 0) atomicOr(&flag, 1);
    __syncthreads();
    const int is32 = flag;

    const int i = blockIdx.x * 256 + tid;
    const float xi = x[i];
    const int lbl = is32 ? t32[i] : t32[2 * i];
    g_x[i] = xi;
    g_lab[i] = (unsigned char)lbl;
    const double xd = (double)xi;
    g_Ad[i] = exp(16.0 * xd);
    g_Bd[i] = exp(-16.0 * xd);
    atomicAdd(&g_cnt[lbl], 1);

    // last-row stats (fixed point, deterministic)
    const float xl = x[N - 1];
    const int   ll = is32 ? t32[N - 1] : t32[2 * (N - 1)];
    float d = fabsf(xl - xi);
    unsigned long long pq = 0ull, nq = 0ull; int pc = 0, nc = 0;
    if (lbl == ll) { if (d < 1.0f) { pq = (unsigned long long)(d * FIXP + 0.5f); pc = 1; } }
    else           { nq = (unsigned long long)(d * FIXP + 0.5f); nc = 1; }
#pragma unroll
    for (int o = 16; o; o >>= 1) {
        pq += __shfl_xor_sync(~0u, pq, o); nq += __shfl_xor_sync(~0u, nq, o);
        pc += __shfl_xor_sync(~0u, pc, o); nc += __shfl_xor_sync(~0u, nc, o);
    }
    const int w = tid >> 5, l = tid & 31;
    if (l == 0) { rps[w] = pq; rns[w] = nq; rpc[w] = pc; rnc[w] = nc; }
    __syncthreads();
    if (tid == 0) {
        unsigned long long sp = 0ull, sn = 0ull; int cp = 0, cn = 0;
        for (int k = 0; k < 8; k++) { sp += rps[k]; sn += rns[k]; cp += rpc[k]; cn += rnc[k]; }
        atomicAdd(&g_ps, sp); atomicAdd(&g_ns, sn);
        atomicAdd(&g_pc, (unsigned)cp); atomicAdd(&g_nc, (unsigned)cn);
    }
}

// ---------------------------------------------------------------------------
// K2 rank+scatter (128 x 256, 64KB smem): compound key (label, x, idx) rank by
// counting; rank == position in concatenated per-label sorted arrays.
// ---------------------------------------------------------------------------
__global__ void __launch_bounds__(256) rank_kernel() {
    extern __shared__ unsigned long long sk[];
    const int tid = threadIdx.x;
    for (int k = tid; k < N; k += 256)
        sk[k] = ((unsigned long long)g_lab[k] << 45)
              | ((unsigned long long)fenc(g_x[k]) << 13)
              | (unsigned)k;
    __syncthreads();

    const int warp = tid >> 5, lane = tid & 31;
    const int row0 = (blockIdx.x * 8 + warp) * 8;
    unsigned long long mykey[8];
    int cnt[8];
#pragma unroll
    for (int r = 0; r < 8; r++) { mykey[r] = sk[row0 + r]; cnt[r] = 0; }

    for (int j = lane; j < N; j += 32) {
        const unsigned long long kj = sk[j];
#pragma unroll
        for (int r = 0; r < 8; r++) cnt[r] += (kj < mykey[r]) ? 1 : 0;
    }
#pragma unroll
    for (int r = 0; r < 8; r++)
#pragma unroll
        for (int o = 16; o; o >>= 1)
            cnt[r] += __shfl_xor_sync(0xffffffffu, cnt[r], o);

    if (lane < 8) {
        int gr = 0;
#pragma unroll
        for (int r = 0; r < 8; r++) if (lane == r) gr = cnt[r];
        const int row = row0 + lane;
        g_xs[gr] = g_x[row];
        g_As[gr] = g_Ad[row];
        g_Bs[gr] = g_Bd[row];
    }
}

// ---------------------------------------------------------------------------
// K3 build (1 x 1024): offsets, per-label min/max, per-label EXCLUSIVE PREFIX
// of A (ascending terms -> window [aa,m) diffs accurate) and per-label SUFFIX
// sums of B (accumulated small->large; window [m,bb) = SB[m]-SB[bb] accurate).
// ---------------------------------------------------------------------------
__global__ void __launch_bounds__(1024, 1) build_kernel() {
    __shared__ int s_off[11], s_cnt[10];
    const int tid = threadIdx.x;
    if (tid == 0) {
        int acc = 0;
        for (int c = 0; c < 10; c++) {
            s_off[c] = acc; g_off[c] = acc;
            int cc = g_cnt[c]; s_cnt[c] = cc; acc += cc;
        }
        s_off[10] = acc; g_off[10] = acc;
        for (int c = 0; c < 10; c++) {
            if (s_cnt[c] > 0) {
                g_mn[c] = g_xs[s_off[c]];
                g_mx[c] = g_xs[s_off[c] + s_cnt[c] - 1];
            }
        }
    }
    __syncthreads();
    const int w = tid >> 5, lane = tid & 31;
    if (w < 20) {
        const int c = w >> 1;
        const int off = s_off[c], L = s_cnt[c];
        const int base = off + c;                       // per-label extra slot
        const int chunk = (L + 31) >> 5;
        int st = lane * chunk; if (st > L) st = L;
        int en = st + chunk;   if (en > L) en = L;

        if ((w & 1) == 0) {
            // A: forward exclusive prefix
            double s = 0.0;
            for (int k = st; k < en; k++) s += g_As[off + k];
            double t = s;
#pragma unroll
            for (int o = 1; o < 32; o <<= 1) {
                double v = __shfl_up_sync(~0u, t, o);
                if (lane >= o) t += v;
            }
            double run = t - s;
            for (int k = st; k < en; k++) { g_PA[base + k] = run; run += g_As[off + k]; }
            if (lane == 31) g_PA[base + L] = run;
        } else {
            // B: suffix sums via reversed inclusive scan (r-index = L-1-k)
            double s = 0.0;
            for (int r = st; r < en; r++) s += g_Bs[off + (L - 1 - r)];
            double t = s;
#pragma unroll
            for (int o = 1; o < 32; o <<= 1) {
                double v = __shfl_up_sync(~0u, t, o);
                if (lane >= o) t += v;
            }
            double run = t - s;
            for (int r = st; r < en; r++) {
                run += g_Bs[off + (L - 1 - r)];
                g_SB[base + (L - 1 - r)] = run;          // SB[k] = sum_{j>=k}
            }
            if (lane == 0) g_SB[base + L] = 0.0;
        }
    }
}

// ---------------------------------------------------------------------------
// K4 query (64 x 128): xs staged in SMEM so every binary-search probe is an
// LDS (29cyc) instead of a dependent LDG (~600cyc). Same exact fp32 predicate
// fabsf(xi - xs[k]) < bound; PA/SB prefix-difference sums; ticket finalize.
// ---------------------------------------------------------------------------
__global__ void __launch_bounds__(QT) query_kernel(float* __restrict__ out) {
    __shared__ float sxs[N];                       // 32 KB
    __shared__ int   s_off[10], s_cnt[10];
    __shared__ float s_mn[10], s_mx[10];
    __shared__ float rls[4]; __shared__ int rpcs[4];
    __shared__ unsigned lastS;
    const int tid = threadIdx.x;
    {
        float4* dst = (float4*)sxs;
        const float4* src = (const float4*)g_xs;
        for (int k = tid; k < N / 4; k += QT) dst[k] = src[k];
    }
    if (tid < 10) {
        s_off[tid] = g_off[tid]; s_cnt[tid] = g_cnt[tid];
        s_mn[tid] = g_mn[tid];   s_mx[tid] = g_mx[tid];
    }
    __syncthreads();

    const int i = blockIdx.x * QT + tid;
    const float xi = g_x[i];
    const int lab = g_lab[i];
    const double Ai = g_Ad[i], Bi = g_Bd[i];

    // phase A: per-label split m_c = first r with xs > xi (10-way interleaved)
    int m[10];
    {
        int lo[10], hi[10];
#pragma unroll
        for (int c = 0; c < 10; c++) { lo[c] = 0; hi[c] = s_cnt[c]; }
        for (int s = 0; s < 14; s++) {
#pragma unroll
            for (int c = 0; c < 10; c++) {
                if (lo[c] < hi[c]) {
                    int mid = (lo[c] + hi[c]) >> 1;
                    if (sxs[s_off[c] + mid] > xi) hi[c] = mid; else lo[c] = mid + 1;
                }
            }
        }
#pragma unroll
        for (int c = 0; c < 10; c++) m[c] = lo[c];
    }

    // phase B: threshold = max(neg extremes, own-label d<1 window endpoints)
    float th;
    {
        const int offl = s_off[lab], ml = m[lab], cl = s_cnt[lab];
        int lo = 0, hi = ml;
        for (int s = 0; s < 14; s++) {
            if (lo < hi) { int mid = (lo + hi) >> 1;
                if (fabsf(xi - sxs[offl + mid]) < 1.0f) hi = mid; else lo = mid + 1; }
        }
        const int a0 = lo;                // a0 < ml always (self has d=0)
        lo = ml; hi = cl;
        for (int s = 0; s < 14; s++) {
            if (lo < hi) { int mid = (lo + hi) >> 1;
                if (fabsf(xi - sxs[offl + mid]) < 1.0f) lo = mid + 1; else hi = mid; }
        }
        const int b0 = lo;
        th = fabsf(xi - sxs[offl + a0]);
        if (b0 > ml) th = fmaxf(th, fabsf(xi - sxs[offl + b0 - 1]));
#pragma unroll
        for (int c = 0; c < 10; c++)
            if (c != lab && s_cnt[c] > 0)
                th = fmaxf(th, fmaxf(fabsf(xi - s_mn[c]), fabsf(xi - s_mx[c])));
    }

    float loss = 0.f;
    if (th > 0.f) {
        const float pm = fminf(1.0f, th);    // pos bound: d<1 AND d<th
        int aa[10], bb[10];
        {
            int lo[10], hi[10];
#pragma unroll
            for (int c = 0; c < 10; c++) { lo[c] = 0; hi[c] = m[c]; }
            for (int s = 0; s < 14; s++) {
#pragma unroll
                for (int c = 0; c < 10; c++) {
                    const float bd = (c == lab) ? pm : th;
                    if (lo[c] < hi[c]) {
                        int mid = (lo[c] + hi[c]) >> 1;
                        if (fabsf(xi - sxs[s_off[c] + mid]) < bd) hi[c] = mid;
                        else lo[c] = mid + 1;
                    }
                }
            }
#pragma unroll
            for (int c = 0; c < 10; c++) aa[c] = lo[c];
#pragma unroll
            for (int c = 0; c < 10; c++) { lo[c] = m[c]; hi[c] = s_cnt[c]; }
            for (int s = 0; s < 14; s++) {
#pragma unroll
                for (int c = 0; c < 10; c++) {
                    const float bd = (c == lab) ? pm : th;
                    if (lo[c] < hi[c]) {
                        int mid = (lo[c] + hi[c]) >> 1;
                        if (fabsf(xi - sxs[s_off[c] + mid]) < bd) lo[c] = mid + 1;
                        else hi[c] = mid;
                    }
                }
            }
#pragma unroll
            for (int c = 0; c < 10; c++) bb[c] = lo[c];
        }
        // e = Bi*Aj (j left of split, window [aa,m)) + Ai*Bj (right, [m,bb))
        double pos = 0.0, neg = 0.0;
#pragma unroll
        for (int c = 0; c < 10; c++) {
            const int e = s_off[c] + c;
            const double v = Bi * (g_PA[e + m[c]] - g_PA[e + aa[c]])
                           + Ai * (g_SB[e + m[c]] - g_SB[e + bb[c]]);
            if (c == lab) pos = v; else neg += v;
        }
        if (pos > 0.0) loss = (float)log((pos + fmax(neg, 0.0)) / pos);
    }

    // fused finalize
    float s = loss; int pc = (loss < 0.6f) ? 1 : 0;
#pragma unroll
    for (int o = 16; o; o >>= 1) {
        s  += __shfl_xor_sync(~0u, s, o);
        pc += __shfl_xor_sync(~0u, pc, o);
    }
    const int w = tid >> 5, lane = tid & 31;
    if (lane == 0) { rls[w] = s; rpcs[w] = pc; }
    __syncthreads();
    if (tid == 0) {
        g_pls[blockIdx.x] = rls[0] + rls[1] + rls[2] + rls[3];
        g_ppc[blockIdx.x] = rpcs[0] + rpcs[1] + rpcs[2] + rpcs[3];
        __threadfence();
        lastS = atomicAdd(&g_ticket, 1u);
    }
    __syncthreads();
    if (lastS == QB - 1) {
        __threadfence();
        if (tid < QB) {
            float v = g_pls[tid]; int c = g_ppc[tid];
#pragma unroll
            for (int o = 16; o; o >>= 1) {
                v += __shfl_xor_sync(~0u, v, o);
                c += __shfl_xor_sync(~0u, c, o);
            }
            if (tid == 0)  { rls[0] = v; rpcs[0] = c; }
            if (tid == 32) { rls[1] = v; rpcs[1] = c; }
        }
        __syncthreads();
        if (tid == 0) {
            out[0] = (rls[0] + rls[1]) / (float)N;
            out[1] = (float)(rpcs[0] + rpcs[1]) / (float)N;
            out[2] = ((float)g_ps / FIXP) / (float)g_pc;
            out[3] = ((float)g_ns / FIXP) / (float)g_nc;
            for (int c = 0; c < 10; c++) g_cnt[c] = 0;   // reset for replay
            g_ps = 0ull; g_ns = 0ull; g_pc = 0u; g_nc = 0u;
            g_ticket = 0u;
        }
    }
}

// ---------------------------------------------------------------------------
extern "C" void kernel_launch(void* const* d_in, const int* in_sizes, int n_in,
                              void* d_out, int out_size) {
    const float* x   = (const float*)d_in[0];
    const int*   t32 = (const int*)d_in[1];
    float*       out = (float*)d_out;

    cudaFuncSetAttribute(rank_kernel,
                         cudaFuncAttributeMaxDynamicSharedMemorySize, 65536);

    prep_kernel<<<32, 256>>>(x, t32);
    rank_kernel<<<128, 256, 65536>>>();
    build_kernel<<<1, 1024>>>();
    query_kernel<<<QB, QT>>>(out);
}

// round 8
// speedup vs baseline: 1.6198x; 1.4037x over previous
#include <cuda_runtime.h>
#include <math.h>

#define N       8192
#define FIXP    4194304.0f      // 2^22 fixed point for last-row stats
#define QB      256             // query blocks
#define QT      320             // 32 rows x 10 labels
#define QROWS   32

// ---- device globals -------------------------------------------------------
__device__ float         g_x[N];
__device__ unsigned char g_lab[N];
__device__ double        g_Ad[N], g_Bd[N];       // exp(+-16x), double
__device__ int           g_cnt[10];
__device__ int           g_off[11];
__device__ float         g_mn[10], g_mx[10];
__device__ float         g_xs[N];                // sorted by (label, x, idx)
__device__ double        g_As[N], g_Bs[N];
__device__ double        g_PA[N + 16];           // per-label EXCLUSIVE prefix of A
__device__ double        g_SB[N + 16];           // per-label SUFFIX sums of B
__device__ float         g_pls[QB];
__device__ int           g_ppc[QB];
__device__ unsigned long long g_ps = 0ull, g_ns = 0ull;
__device__ unsigned g_pc = 0u, g_nc = 0u;
__device__ unsigned g_ticket = 0u;

__device__ __forceinline__ unsigned fenc(float f) {    // order-preserving key
    unsigned u = __float_as_uint(f);
    return (u & 0x80000000u) ? ~u : (u | 0x80000000u);
}

// ---------------------------------------------------------------------------
// K1 prep (32 x 256): dtype-layout detect (JAX demotes int64->int32; odd words
// of first 16KB zero iff true int64), decode, double exp tables, label
// histogram, last-row stats (deterministic fixed-point atomics).
// ---------------------------------------------------------------------------
__global__ void __launch_bounds__(256) prep_kernel(const float* __restrict__ x,
                                                   const int* __restrict__ t32) {
    __shared__ int flag;
    __shared__ unsigned long long rps[8], rns[8];
    __shared__ int rpc[8], rnc[8];
    __shared__ int hcnt[10];
    const int tid = threadIdx.x;
    if (tid == 0) flag = 0;
    if (tid < 10) hcnt[tid] = 0;
    __syncthreads();
    for (int k = tid; k < 2048; k += 256)
        if (t32[2 * k + 1] != 0) atomicOr(&flag, 1);
    __syncthreads();
    const int is32 = flag;

    const int i = blockIdx.x * 256 + tid;
    const float xi = x[i];
    const int lbl = is32 ? t32[i] : t32[2 * i];
    g_x[i] = xi;
    g_lab[i] = (unsigned char)lbl;
    const double xd = (double)xi;
    g_Ad[i] = exp(16.0 * xd);
    g_Bd[i] = exp(-16.0 * xd);
    atomicAdd(&hcnt[lbl], 1);                  // block-local histogram

    // last-row stats (fixed point, deterministic)
    const float xl = x[N - 1];
    const int   ll = is32 ? t32[N - 1] : t32[2 * (N - 1)];
    float d = fabsf(xl - xi);
    unsigned long long pq = 0ull, nq = 0ull; int pc = 0, nc = 0;
    if (lbl == ll) { if (d < 1.0f) { pq = (unsigned long long)(d * FIXP + 0.5f); pc = 1; } }
    else           { nq = (unsigned long long)(d * FIXP + 0.5f); nc = 1; }
#pragma unroll
    for (int o = 16; o; o >>= 1) {
        pq += __shfl_xor_sync(~0u, pq, o); nq += __shfl_xor_sync(~0u, nq, o);
        pc += __shfl_xor_sync(~0u, pc, o); nc += __shfl_xor_sync(~0u, nc, o);
    }
    const int w = tid >> 5, l = tid & 31;
    if (l == 0) { rps[w] = pq; rns[w] = nq; rpc[w] = pc; rnc[w] = nc; }
    __syncthreads();
    if (tid == 0) {
        unsigned long long sp = 0ull, sn = 0ull; int cp = 0, cn = 0;
        for (int k = 0; k < 8; k++) { sp += rps[k]; sn += rns[k]; cp += rpc[k]; cn += rnc[k]; }
        atomicAdd(&g_ps, sp); atomicAdd(&g_ns, sn);
        atomicAdd(&g_pc, (unsigned)cp); atomicAdd(&g_nc, (unsigned)cn);
    }
    if (tid < 10) atomicAdd(&g_cnt[tid], hcnt[tid]);
}

// ---------------------------------------------------------------------------
// K2 rank+scatter (128 x 256, 64KB smem): compound key (label, x, idx) rank by
// counting; rank == position in concatenated per-label sorted arrays.
// ---------------------------------------------------------------------------
__global__ void __launch_bounds__(256) rank_kernel() {
    extern __shared__ unsigned long long sk[];
    const int tid = threadIdx.x;
    for (int k = tid; k < N; k += 256)
        sk[k] = ((unsigned long long)g_lab[k] << 45)
              | ((unsigned long long)fenc(g_x[k]) << 13)
              | (unsigned)k;
    __syncthreads();

    const int warp = tid >> 5, lane = tid & 31;
    const int row0 = (blockIdx.x * 8 + warp) * 8;
    unsigned long long mykey[8];
    int cnt[8];
#pragma unroll
    for (int r = 0; r < 8; r++) { mykey[r] = sk[row0 + r]; cnt[r] = 0; }

    for (int j = lane; j < N; j += 32) {
        const unsigned long long kj = sk[j];
#pragma unroll
        for (int r = 0; r < 8; r++) cnt[r] += (kj < mykey[r]) ? 1 : 0;
    }
#pragma unroll
    for (int r = 0; r < 8; r++)
#pragma unroll
        for (int o = 16; o; o >>= 1)
            cnt[r] += __shfl_xor_sync(0xffffffffu, cnt[r], o);

    if (lane < 8) {
        int gr = 0;
#pragma unroll
        for (int r = 0; r < 8; r++) if (lane == r) gr = cnt[r];
        const int row = row0 + lane;
        g_xs[gr] = g_x[row];
        g_As[gr] = g_Ad[row];
        g_Bs[gr] = g_Bd[row];
    }
}

// ---------------------------------------------------------------------------
// K3 build (1 x 1024): offsets, per-label min/max, per-label EXCLUSIVE PREFIX
// of A (ascending terms) and per-label SUFFIX sums of B (small->large).
// ---------------------------------------------------------------------------
__global__ void __launch_bounds__(1024, 1) build_kernel() {
    __shared__ int s_off[11], s_cnt[10];
    const int tid = threadIdx.x;
    if (tid == 0) {
        int acc = 0;
        for (int c = 0; c < 10; c++) {
            s_off[c] = acc; g_off[c] = acc;
            int cc = g_cnt[c]; s_cnt[c] = cc; acc += cc;
        }
        s_off[10] = acc; g_off[10] = acc;
        for (int c = 0; c < 10; c++) {
            if (s_cnt[c] > 0) {
                g_mn[c] = g_xs[s_off[c]];
                g_mx[c] = g_xs[s_off[c] + s_cnt[c] - 1];
            }
        }
    }
    __syncthreads();
    const int w = tid >> 5, lane = tid & 31;
    if (w < 20) {
        const int c = w >> 1;
        const int off = s_off[c], L = s_cnt[c];
        const int base = off + c;                       // per-label extra slot
        const int chunk = (L + 31) >> 5;
        int st = lane * chunk; if (st > L) st = L;
        int en = st + chunk;   if (en > L) en = L;

        if ((w & 1) == 0) {
            double s = 0.0;
            for (int k = st; k < en; k++) s += g_As[off + k];
            double t = s;
#pragma unroll
            for (int o = 1; o < 32; o <<= 1) {
                double v = __shfl_up_sync(~0u, t, o);
                if (lane >= o) t += v;
            }
            double run = t - s;
            for (int k = st; k < en; k++) { g_PA[base + k] = run; run += g_As[off + k]; }
            if (lane == 31) g_PA[base + L] = run;
        } else {
            double s = 0.0;
            for (int r = st; r < en; r++) s += g_Bs[off + (L - 1 - r)];
            double t = s;
#pragma unroll
            for (int o = 1; o < 32; o <<= 1) {
                double v = __shfl_up_sync(~0u, t, o);
                if (lane >= o) t += v;
            }
            double run = t - s;
            for (int r = st; r < en; r++) {
                run += g_Bs[off + (L - 1 - r)];
                g_SB[base + (L - 1 - r)] = run;          // SB[k] = sum_{j>=k}
            }
            if (lane == 0) g_SB[base + L] = 0.0;
        }
    }
}

// ---------------------------------------------------------------------------
// K4 query (256 x 320): one thread per (row, label). All search state scalar
// (no spills), xs staged in SMEM. Same exact fp32 predicates as before.
// ---------------------------------------------------------------------------
__global__ void __launch_bounds__(QT) query_kernel(float* __restrict__ out) {
    __shared__ float  sxs[N];                    // 32 KB
    __shared__ int    s_off[10], s_cnt[10];
    __shared__ float  s_mn[10], s_mx[10];
    __shared__ float  s_cand[QROWS][10];
    __shared__ double s_v[QROWS][10];
    __shared__ float  s_loss[QROWS];
    __shared__ float  rls[8]; __shared__ int rpcs[8];
    __shared__ unsigned lastS;
    const int tid = threadIdx.x;
    {
        float4* dst = (float4*)sxs;
        const float4* src = (const float4*)g_xs;
        for (int k = tid; k < N / 4; k += QT) dst[k] = src[k];
    }
    if (tid < 10) {
        s_off[tid] = g_off[tid]; s_cnt[tid] = g_cnt[tid];
        s_mn[tid] = g_mn[tid];   s_mx[tid] = g_mx[tid];
    }
    __syncthreads();

    const int y = tid / 10, c = tid - y * 10;    // row-in-block, label
    const int i = blockIdx.x * QROWS + y;        // global row
    const float xi  = g_x[i];
    const int   lab = g_lab[i];
    const int   off = s_off[c], cnt = s_cnt[c];
    const bool  own = (c == lab);

    // m: first index in label-c segment with xs > xi
    int lo = 0, hi = cnt;
    for (int s = 0; s < 14; s++) {
        if (lo < hi) { int mid = (lo + hi) >> 1;
            if (sxs[off + mid] > xi) hi = mid; else lo = mid + 1; }
    }
    const int m = lo;

    // threshold candidate for this label
    float cand = 0.f;
    if (own) {
        // left: first in [0,m) with d<1 (d decreasing right-ward => monotone)
        lo = 0; hi = m;
        for (int s = 0; s < 14; s++) {
            if (lo < hi) { int mid = (lo + hi) >> 1;
                if (fabsf(xi - sxs[off + mid]) < 1.0f) hi = mid; else lo = mid + 1; }
        }
        const int a0 = lo;                       // a0 < m (self d=0)
        cand = fabsf(xi - sxs[off + a0]);
        // right: first in [m,cnt) with d>=1
        lo = m; hi = cnt;
        for (int s = 0; s < 14; s++) {
            if (lo < hi) { int mid = (lo + hi) >> 1;
                if (fabsf(xi - sxs[off + mid]) < 1.0f) lo = mid + 1; else hi = mid; }
        }
        if (lo > m) cand = fmaxf(cand, fabsf(xi - sxs[off + lo - 1]));
    } else if (cnt > 0) {
        cand = fmaxf(fabsf(xi - s_mn[c]), fabsf(xi - s_mx[c]));
    }
    s_cand[y][c] = cand;
    __syncthreads();

    float th = s_cand[y][0];
#pragma unroll
    for (int k = 1; k < 10; k++) th = fmaxf(th, s_cand[y][k]);
    const float pm = fminf(1.0f, th);
    const float bd = own ? pm : th;

    // aa: first in [0,m) with d<bd ; bb: first in [m,cnt) with d>=bd
    lo = 0; hi = m;
    for (int s = 0; s < 14; s++) {
        if (lo < hi) { int mid = (lo + hi) >> 1;
            if (fabsf(xi - sxs[off + mid]) < bd) hi = mid; else lo = mid + 1; }
    }
    const int aa = lo;
    lo = m; hi = cnt;
    for (int s = 0; s < 14; s++) {
        if (lo < hi) { int mid = (lo + hi) >> 1;
            if (fabsf(xi - sxs[off + mid]) < bd) lo = mid + 1; else hi = mid; }
    }
    const int bb = lo;

    {
        const double Ai = g_Ad[i], Bi = g_Bd[i];
        const int e = off + c;                   // per-label prefix base
        s_v[y][c] = Bi * (g_PA[e + m] - g_PA[e + aa])
                  + Ai * (g_SB[e + m] - g_SB[e + bb]);
    }
    __syncthreads();

    if (c == 0) {
        double pos = s_v[y][lab], neg = 0.0;
#pragma unroll
        for (int k = 0; k < 10; k++) if (k != lab) neg += s_v[y][k];
        float loss = 0.f;
        if (th > 0.f && pos > 0.0)
            loss = (float)log((pos + fmax(neg, 0.0)) / pos);
        s_loss[y] = loss;
    }
    __syncthreads();

    // block partial: 32 rows
    if (tid < 32) {
        float l = s_loss[tid];
        int   p = (l < 0.6f) ? 1 : 0;
#pragma unroll
        for (int o = 16; o; o >>= 1) {
            l += __shfl_xor_sync(~0u, l, o);
            p += __shfl_xor_sync(~0u, p, o);
        }
        if (tid == 0) {
            g_pls[blockIdx.x] = l;
            g_ppc[blockIdx.x] = p;
            __threadfence();
            lastS = atomicAdd(&g_ticket, 1u);
        }
    }
    __syncthreads();
    if (lastS == QB - 1) {                        // last block finalizes
        __threadfence();
        if (tid < QB) {
            float v = g_pls[tid]; int p = g_ppc[tid];
#pragma unroll
            for (int o = 16; o; o >>= 1) {
                v += __shfl_xor_sync(~0u, v, o);
                p += __shfl_xor_sync(~0u, p, o);
            }
            if ((tid & 31) == 0) { rls[tid >> 5] = v; rpcs[tid >> 5] = p; }
        }
        __syncthreads();
        if (tid == 0) {
            float fs = 0.f; int fc = 0;
            for (int k = 0; k < 8; k++) { fs += rls[k]; fc += rpcs[k]; }
            out[0] = fs / (float)N;
            out[1] = (float)fc / (float)N;
            out[2] = ((float)g_ps / FIXP) / (float)g_pc;
            out[3] = ((float)g_ns / FIXP) / (float)g_nc;
            for (int k = 0; k < 10; k++) g_cnt[k] = 0;   // reset for replay
            g_ps = 0ull; g_ns = 0ull; g_pc = 0u; g_nc = 0u;
            g_ticket = 0u;
        }
    }
}

// ---------------------------------------------------------------------------
extern "C" void kernel_launch(void* const* d_in, const int* in_sizes, int n_in,
                              void* d_out, int out_size) {
    const float* x   = (const float*)d_in[0];
    const int*   t32 = (const int*)d_in[1];
    float*       out = (float*)d_out;

    cudaFuncSetAttribute(rank_kernel,
                         cudaFuncAttributeMaxDynamicSharedMemorySize, 65536);

    prep_kernel<<<32, 256>>>(x, t32);
    rank_kernel<<<128, 256, 65536>>>();
    build_kernel<<<1, 1024>>>();
    query_kernel<<<QB, QT>>>(out);
}

// round 9
// speedup vs baseline: 1.7645x; 1.0893x over previous
#include <cuda_runtime.h>
#include <math.h>

#define N       8192
#define FIXP    4194304.0f      // 2^22 fixed point for last-row stats
#define QB      256             // query blocks
#define QT      320             // 32 rows x 10 labels
#define QROWS   32

// ---- device globals -------------------------------------------------------
__device__ float         g_x[N];
__device__ unsigned char g_lab[N];
__device__ double        g_Ad[N], g_Bd[N];       // exp(+-16x), double
__device__ int           g_cnt[10];
__device__ int           g_off[11];
__device__ float         g_mn[10], g_mx[10];
__device__ float         g_xs[N];                // sorted by (label, x, idx)
__device__ double        g_As[N], g_Bs[N];
__device__ double        g_PA[N + 16];           // per-label EXCLUSIVE prefix of A
__device__ double        g_SB[N + 16];           // per-label SUFFIX sums of B
__device__ float         g_pls[QB];
__device__ int           g_ppc[QB];
__device__ unsigned long long g_ps = 0ull, g_ns = 0ull;
__device__ unsigned g_pc = 0u, g_nc = 0u;
__device__ unsigned g_ticket = 0u;

__device__ __forceinline__ unsigned fenc(float f) {    // order-preserving key
    unsigned u = __float_as_uint(f);
    return (u & 0x80000000u) ? ~u : (u | 0x80000000u);
}

// Combined-monotone searches over a whole label segment [off, off+cnt).
// left:  first k with ((xs[k] <= xi) ? fabsf(xi-xs[k]) < bd : true)
//        == first LEFT-side element inside the d<bd window (or m if none).
// right: first k with ((xs[k] > xi) && !(fabsf(xi-xs[k]) < bd))
//        == end (exclusive) of the RIGHT-side d<bd window.
// Both predicates are monotone along sorted xs and use the EXACT fp32
// membership test fabsf(xi - xs[k]) < bd of the reference.
__device__ __forceinline__ int search_left(const float* sxs, int off, int cnt,
                                           float xi, float bd) {
    int lo = 0, hi = cnt;
#pragma unroll 1
    for (int s = 0; s < 14; s++) {
        if (lo < hi) {
            int mid = (lo + hi) >> 1;
            float xv = sxs[off + mid];
            bool p = (xv <= xi) ? (fabsf(xi - xv) < bd) : true;
            if (p) hi = mid; else lo = mid + 1;
        }
    }
    return lo;
}
__device__ __forceinline__ int search_right(const float* sxs, int off, int cnt,
                                            float xi, float bd) {
    int lo = 0, hi = cnt;
#pragma unroll 1
    for (int s = 0; s < 14; s++) {
        if (lo < hi) {
            int mid = (lo + hi) >> 1;
            float xv = sxs[off + mid];
            bool p = (xv > xi) && !(fabsf(xi - xv) < bd);
            if (p) hi = mid; else lo = mid + 1;
        }
    }
    return lo;
}

// ---------------------------------------------------------------------------
// K1 prep (32 x 256): dtype-layout detect (JAX demotes int64->int32; odd words
// of first 16KB zero iff true int64), decode, double exp tables, label
// histogram, last-row stats (deterministic fixed-point atomics).
// ---------------------------------------------------------------------------
__global__ void __launch_bounds__(256) prep_kernel(const float* __restrict__ x,
                                                   const int* __restrict__ t32) {
    __shared__ int flag;
    __shared__ unsigned long long rps[8], rns[8];
    __shared__ int rpc[8], rnc[8];
    __shared__ int hcnt[10];
    const int tid = threadIdx.x;
    if (tid == 0) flag = 0;
    if (tid < 10) hcnt[tid] = 0;
    __syncthreads();
    for (int k = tid; k < 2048; k += 256)
        if (t32[2 * k + 1] != 0) atomicOr(&flag, 1);
    __syncthreads();
    const int is32 = flag;

    const int i = blockIdx.x * 256 + tid;
    const float xi = x[i];
    const int lbl = is32 ? t32[i] : t32[2 * i];
    g_x[i] = xi;
    g_lab[i] = (unsigned char)lbl;
    const double xd = (double)xi;
    g_Ad[i] = exp(16.0 * xd);
    g_Bd[i] = exp(-16.0 * xd);
    atomicAdd(&hcnt[lbl], 1);

    const float xl = x[N - 1];
    const int   ll = is32 ? t32[N - 1] : t32[2 * (N - 1)];
    float d = fabsf(xl - xi);
    unsigned long long pq = 0ull, nq = 0ull; int pc = 0, nc = 0;
    if (lbl == ll) { if (d < 1.0f) { pq = (unsigned long long)(d * FIXP + 0.5f); pc = 1; } }
    else           { nq = (unsigned long long)(d * FIXP + 0.5f); nc = 1; }
#pragma unroll
    for (int o = 16; o; o >>= 1) {
        pq += __shfl_xor_sync(~0u, pq, o); nq += __shfl_xor_sync(~0u, nq, o);
        pc += __shfl_xor_sync(~0u, pc, o); nc += __shfl_xor_sync(~0u, nc, o);
    }
    const int w = tid >> 5, l = tid & 31;
    if (l == 0) { rps[w] = pq; rns[w] = nq; rpc[w] = pc; rnc[w] = nc; }
    __syncthreads();
    if (tid == 0) {
        unsigned long long sp = 0ull, sn = 0ull; int cp = 0, cn = 0;
        for (int k = 0; k < 8; k++) { sp += rps[k]; sn += rns[k]; cp += rpc[k]; cn += rnc[k]; }
        atomicAdd(&g_ps, sp); atomicAdd(&g_ns, sn);
        atomicAdd(&g_pc, (unsigned)cp); atomicAdd(&g_nc, (unsigned)cn);
    }
    if (tid < 10) atomicAdd(&g_cnt[tid], hcnt[tid]);
}

// ---------------------------------------------------------------------------
// K2 rank+scatter (128 x 256, 64KB smem): compound key (label, x, idx) rank by
// counting; rank == position in concatenated per-label sorted arrays.
// ---------------------------------------------------------------------------
__global__ void __launch_bounds__(256) rank_kernel() {
    extern __shared__ unsigned long long sk[];
    const int tid = threadIdx.x;
    for (int k = tid; k < N; k += 256)
        sk[k] = ((unsigned long long)g_lab[k] << 45)
              | ((unsigned long long)fenc(g_x[k]) << 13)
              | (unsigned)k;
    __syncthreads();

    const int warp = tid >> 5, lane = tid & 31;
    const int row0 = (blockIdx.x * 8 + warp) * 8;
    unsigned long long mykey[8];
    int cnt[8];
#pragma unroll
    for (int r = 0; r < 8; r++) { mykey[r] = sk[row0 + r]; cnt[r] = 0; }

    for (int j = lane; j < N; j += 32) {
        const unsigned long long kj = sk[j];
#pragma unroll
        for (int r = 0; r < 8; r++) cnt[r] += (kj < mykey[r]) ? 1 : 0;
    }
#pragma unroll
    for (int r = 0; r < 8; r++)
#pragma unroll
        for (int o = 16; o; o >>= 1)
            cnt[r] += __shfl_xor_sync(0xffffffffu, cnt[r], o);

    if (lane < 8) {
        int gr = 0;
#pragma unroll
        for (int r = 0; r < 8; r++) if (lane == r) gr = cnt[r];
        const int row = row0 + lane;
        g_xs[gr] = g_x[row];
        g_As[gr] = g_Ad[row];
        g_Bs[gr] = g_Bd[row];
    }
}

// ---------------------------------------------------------------------------
// K3 build (1 x 1024, 128KB dyn smem): stage As/Bs in SMEM (coalesced, MLP),
// then per-(label,array) warp scans hit LDS (29cyc) not LDG (~600cyc).
// PA = per-label EXCLUSIVE prefix of A; SB = per-label SUFFIX sums of B.
// ---------------------------------------------------------------------------
__global__ void __launch_bounds__(1024, 1) build_kernel() {
    extern __shared__ double sAB[];              // sA[0..N), sB[N..2N)
    double* sA = sAB;
    double* sB = sAB + N;
    __shared__ int s_off[11], s_cnt[10];
    const int tid = threadIdx.x;

    {   // coalesced stage: 2 * 64KB
        double2* dA = (double2*)sA;
        double2* dB = (double2*)sB;
        const double2* gA = (const double2*)g_As;
        const double2* gB = (const double2*)g_Bs;
        for (int k = tid; k < N / 2; k += 1024) { dA[k] = gA[k]; dB[k] = gB[k]; }
    }
    if (tid == 0) {
        int acc = 0;
        for (int c = 0; c < 10; c++) {
            s_off[c] = acc; g_off[c] = acc;
            int cc = g_cnt[c]; s_cnt[c] = cc; acc += cc;
        }
        s_off[10] = acc; g_off[10] = acc;
    }
    __syncthreads();
    if (tid < 10 && s_cnt[tid] > 0) {
        g_mn[tid] = g_xs[s_off[tid]];
        g_mx[tid] = g_xs[s_off[tid] + s_cnt[tid] - 1];
    }

    const int w = tid >> 5, lane = tid & 31;
    if (w < 20) {
        const int c = w >> 1;
        const int off = s_off[c], L = s_cnt[c];
        const int base = off + c;                       // per-label extra slot
        const int chunk = (L + 31) >> 5;
        int st = lane * chunk; if (st > L) st = L;
        int en = st + chunk;   if (en > L) en = L;

        if ((w & 1) == 0) {
            double s = 0.0;
            for (int k = st; k < en; k++) s += sA[off + k];
            double t = s;
#pragma unroll
            for (int o = 1; o < 32; o <<= 1) {
                double v = __shfl_up_sync(~0u, t, o);
                if (lane >= o) t += v;
            }
            double run = t - s;
            for (int k = st; k < en; k++) { g_PA[base + k] = run; run += sA[off + k]; }
            if (lane == 31) g_PA[base + L] = run;
        } else {
            double s = 0.0;
            for (int r = st; r < en; r++) s += sB[off + (L - 1 - r)];
            double t = s;
#pragma unroll
            for (int o = 1; o < 32; o <<= 1) {
                double v = __shfl_up_sync(~0u, t, o);
                if (lane >= o) t += v;
            }
            double run = t - s;
            for (int r = st; r < en; r++) {
                run += sB[off + (L - 1 - r)];
                g_SB[base + (L - 1 - r)] = run;          // SB[k] = sum_{j>=k}
            }
            if (lane == 0) g_SB[base + L] = 0.0;
        }
    }
}

// ---------------------------------------------------------------------------
// K4 query (256 x 320): thread = (row y, label c). Chain-shortened:
//  - non-own labels skip window searches unless extreme distance ties th
//  - own-label candidate + window searches distributed to helper threads
//    (lab+1)%10 / (lab+2)%10 using range-free combined-monotone predicates.
// All membership tests bit-identical to R8 (which passed at 1.28e-7).
// ---------------------------------------------------------------------------
__global__ void __launch_bounds__(QT) query_kernel(float* __restrict__ out) {
    __shared__ float  sxs[N];                    // 32 KB
    __shared__ int    s_off[10], s_cnt[10];
    __shared__ float  s_mn[10], s_mx[10];
    __shared__ int    s_m[QROWS][10];
    __shared__ float  s_cand[QROWS][12];
    __shared__ int    s_ab[QROWS][2];
    __shared__ double s_v[QROWS][10];
    __shared__ float  s_loss[QROWS];
    __shared__ float  rls[8]; __shared__ int rpcs[8];
    __shared__ unsigned lastS;
    const int tid = threadIdx.x;
    {
        float4* dst = (float4*)sxs;
        const float4* src = (const float4*)g_xs;
        for (int k = tid; k < N / 4; k += QT) dst[k] = src[k];
    }
    if (tid < 10) {
        s_off[tid] = g_off[tid]; s_cnt[tid] = g_cnt[tid];
        s_mn[tid] = g_mn[tid];   s_mx[tid] = g_mx[tid];
    }
    __syncthreads();

    const int y = tid / 10, c = tid - y * 10;    // row-in-block, label
    const int i = blockIdx.x * QROWS + y;        // global row
    const float xi  = g_x[i];
    const int   lab = g_lab[i];
    const int   off = s_off[c], cnt = s_cnt[c];
    const int   a1 = (lab + 1) % 10, a2 = (lab + 2) % 10;
    const int   offL = s_off[lab], cntL = s_cnt[lab];

    // phase 1: split m_c = first index with xs > xi; helpers also run the
    // own-label d<1 boundary searches (range-free, no m dependency).
    int lo = 0, hi = cnt;
#pragma unroll 1
    for (int s = 0; s < 14; s++) {
        if (lo < hi) { int mid = (lo + hi) >> 1;
            if (sxs[off + mid] > xi) hi = mid; else lo = mid + 1; }
    }
    const int m = lo;
    s_m[y][c] = m;
    int a0 = 0, b0 = 0;
    if (c == a1) a0 = search_left (sxs, offL, cntL, xi, 1.0f);
    if (c == a2) b0 = search_right(sxs, offL, cntL, xi, 1.0f);
    __syncthreads();

    // candidates: per-label extreme distances (non-own), own d<1 endpoints
    s_cand[y][c] = (c != lab && cnt > 0)
        ? fmaxf(fabsf(xi - s_mn[c]), fabsf(xi - s_mx[c])) : 0.f;
    if (c == a1) s_cand[y][10] = fabsf(xi - sxs[offL + a0]);   // a0 < m_lab (self)
    if (c == a2) {
        int ml = s_m[y][lab];
        s_cand[y][11] = (b0 > ml) ? fabsf(xi - sxs[offL + b0 - 1]) : 0.f;
    }
    __syncthreads();

    float th = s_cand[y][0];
#pragma unroll
    for (int k = 1; k < 12; k++) th = fmaxf(th, s_cand[y][k]);
    const float pm = fminf(1.0f, th);

    // phase 2: window ends. Non-own: whole segment unless extreme ties th.
    int aa = 0, bb = 0;
    if (cnt > 0 && c != lab) {
        float dmn = fabsf(xi - s_mn[c]);
        float dmx = fabsf(xi - s_mx[c]);
        aa = (dmn < th) ? 0   : search_left (sxs, off, cnt, xi, th);
        bb = (dmx < th) ? cnt : search_right(sxs, off, cnt, xi, th);
    }
    if (c == a1) s_ab[y][0] = search_left (sxs, offL, cntL, xi, pm);
    if (c == a2) s_ab[y][1] = search_right(sxs, offL, cntL, xi, pm);
    __syncthreads();
    if (c == lab) { aa = s_ab[y][0]; bb = s_ab[y][1]; }

    {   // e = Bi*Aj for left window [aa,m), Ai*Bj for right window [m,bb)
        const double Ai = g_Ad[i], Bi = g_Bd[i];
        const int e = off + c;
        s_v[y][c] = Bi * (g_PA[e + m] - g_PA[e + aa])
                  + Ai * (g_SB[e + m] - g_SB[e + bb]);
    }
    __syncthreads();

    if (c == 0) {
        double pos = s_v[y][lab], neg = 0.0;
#pragma unroll
        for (int k = 0; k < 10; k++) if (k != lab) neg += s_v[y][k];
        float loss = 0.f;
        if (th > 0.f && pos > 0.0)
            loss = (float)log((pos + fmax(neg, 0.0)) / pos);
        s_loss[y] = loss;
    }
    __syncthreads();

    if (tid < 32) {
        float l = s_loss[tid];
        int   p = (l < 0.6f) ? 1 : 0;
#pragma unroll
        for (int o = 16; o; o >>= 1) {
            l += __shfl_xor_sync(~0u, l, o);
            p += __shfl_xor_sync(~0u, p, o);
        }
        if (tid == 0) {
            g_pls[blockIdx.x] = l;
            g_ppc[blockIdx.x] = p;
            __threadfence();
            lastS = atomicAdd(&g_ticket, 1u);
        }
    }
    __syncthreads();
    if (lastS == QB - 1) {                        // last block finalizes
        __threadfence();
        if (tid < QB) {
            float v = g_pls[tid]; int p = g_ppc[tid];
#pragma unroll
            for (int o = 16; o; o >>= 1) {
                v += __shfl_xor_sync(~0u, v, o);
                p += __shfl_xor_sync(~0u, p, o);
            }
            if ((tid & 31) == 0) { rls[tid >> 5] = v; rpcs[tid >> 5] = p; }
        }
        __syncthreads();
        if (tid == 0) {
            float fs = 0.f; int fc = 0;
            for (int k = 0; k < 8; k++) { fs += rls[k]; fc += rpcs[k]; }
            out[0] = fs / (float)N;
            out[1] = (float)fc / (float)N;
            out[2] = ((float)g_ps / FIXP) / (float)g_pc;
            out[3] = ((float)g_ns / FIXP) / (float)g_nc;
            for (int k = 0; k < 10; k++) g_cnt[k] = 0;   // reset for replay
            g_ps = 0ull; g_ns = 0ull; g_pc = 0u; g_nc = 0u;
            g_ticket = 0u;
        }
    }
}

// ---------------------------------------------------------------------------
extern "C" void kernel_launch(void* const* d_in, const int* in_sizes, int n_in,
                              void* d_out, int out_size) {
    const float* x   = (const float*)d_in[0];
    const int*   t32 = (const int*)d_in[1];
    float*       out = (float*)d_out;

    cudaFuncSetAttribute(rank_kernel,
                         cudaFuncAttributeMaxDynamicSharedMemorySize, 65536);
    cudaFuncSetAttribute(build_kernel,
                         cudaFuncAttributeMaxDynamicSharedMemorySize, 2 * N * 8);

    prep_kernel<<<32, 256>>>(x, t32);
    rank_kernel<<<128, 256, 65536>>>();
    build_kernel<<<1, 1024, 2 * N * 8>>>();
    query_kernel<<<QB, QT>>>(out);
}

// round 10
// speedup vs baseline: 1.8733x; 1.0617x over previous
#include <cuda_runtime.h>
#include <math.h>

#define N       8192
#define FIXP    4194304.0f      // 2^22 fixed point for last-row stats
#define QB      256             // query blocks
#define QT      320             // 32 rows x 10 labels
#define QROWS   32

// ---- float-float (Dekker two-sum) helpers: ~1e-14 relative, fp32 pipe only -
struct ff { float h, l; };
__device__ __forceinline__ ff ff_add_f(ff x, float a) {
    float s  = x.h + a;
    float bv = s - x.h;
    float e  = (x.h - (s - bv)) + (a - bv);
    float l2 = x.l + e;
    float t  = s + l2;
    ff r; r.h = t; r.l = l2 - (t - s); return r;
}
__device__ __forceinline__ ff ff_add_ff(ff x, ff y) {
    float s  = x.h + y.h;
    float bv = s - x.h;
    float e  = (x.h - (s - bv)) + (y.h - bv) + x.l + y.l;
    float t  = s + e;
    ff r; r.h = t; r.l = e - (t - s); return r;
}

// ---- device globals -------------------------------------------------------
__device__ float         g_x[N];
__device__ unsigned char g_lab[N];
__device__ float         g_A[N], g_B[N];         // expf(+-16x)
__device__ int           g_cnt[10];
__device__ int           g_off[11];
__device__ float         g_mn[10], g_mx[10];
__device__ float         g_xs[N];                // sorted by (label, x, idx)
__device__ float         g_As[N], g_Bs[N];
__device__ float2        g_PA[N + 16];           // per-label EXCLUSIVE ff prefix of A
__device__ float2        g_SB[N + 16];           // per-label ff SUFFIX sums of B
__device__ float         g_pls[QB];
__device__ int           g_ppc[QB];
__device__ unsigned long long g_ps = 0ull, g_ns = 0ull;
__device__ unsigned g_pc = 0u, g_nc = 0u;
__device__ unsigned g_ticket = 0u;

__device__ __forceinline__ unsigned fenc(float f) {    // order-preserving key
    unsigned u = __float_as_uint(f);
    return (u & 0x80000000u) ? ~u : (u | 0x80000000u);
}

// ---------------------------------------------------------------------------
// K1 prep (32 x 256): dtype-layout detect (JAX demotes int64->int32; odd words
// of first 16KB zero iff true int64), decode, FLOAT exp tables, label
// histogram, last-row stats (deterministic fixed-point atomics).
// ---------------------------------------------------------------------------
__global__ void __launch_bounds__(256) prep_kernel(const float* __restrict__ x,
                                                   const int* __restrict__ t32) {
    __shared__ int flag;
    __shared__ unsigned long long rps[8], rns[8];
    __shared__ int rpc[8], rnc[8];
    __shared__ int hcnt[10];
    const int tid = threadIdx.x;
    if (tid == 0) flag = 0;
    if (tid < 10) hcnt[tid] = 0;
    __syncthreads();
    for (int k = tid; k < 2048; k += 256)
        if (t32[2 * k + 1] != 0) atomicOr(&flag, 1);
    __syncthreads();
    const int is32 = flag;

    const int i = blockIdx.x * 256 + tid;
    const float xi = x[i];
    const int lbl = is32 ? t32[i] : t32[2 * i];
    g_x[i] = xi;
    g_lab[i] = (unsigned char)lbl;
    g_A[i] = expf(16.0f * xi);
    g_B[i] = expf(-16.0f * xi);
    atomicAdd(&hcnt[lbl], 1);

    const float xl = x[N - 1];
    const int   ll = is32 ? t32[N - 1] : t32[2 * (N - 1)];
    float d = fabsf(xl - xi);
    unsigned long long pq = 0ull, nq = 0ull; int pc = 0, nc = 0;
    if (lbl == ll) { if (d < 1.0f) { pq = (unsigned long long)(d * FIXP + 0.5f); pc = 1; } }
    else           { nq = (unsigned long long)(d * FIXP + 0.5f); nc = 1; }
#pragma unroll
    for (int o = 16; o; o >>= 1) {
        pq += __shfl_xor_sync(~0u, pq, o); nq += __shfl_xor_sync(~0u, nq, o);
        pc += __shfl_xor_sync(~0u, pc, o); nc += __shfl_xor_sync(~0u, nc, o);
    }
    const int w = tid >> 5, l = tid & 31;
    if (l == 0) { rps[w] = pq; rns[w] = nq; rpc[w] = pc; rnc[w] = nc; }
    __syncthreads();
    if (tid == 0) {
        unsigned long long sp = 0ull, sn = 0ull; int cp = 0, cn = 0;
        for (int k = 0; k < 8; k++) { sp += rps[k]; sn += rns[k]; cp += rpc[k]; cn += rnc[k]; }
        atomicAdd(&g_ps, sp); atomicAdd(&g_ns, sn);
        atomicAdd(&g_pc, (unsigned)cp); atomicAdd(&g_nc, (unsigned)cn);
    }
    if (tid < 10) atomicAdd(&g_cnt[tid], hcnt[tid]);
}

// ---------------------------------------------------------------------------
// K2 rank+scatter (128 x 256, 64KB smem): compound key (label, x, idx) rank by
// counting; rank == position in concatenated per-label sorted arrays.
// ---------------------------------------------------------------------------
__global__ void __launch_bounds__(256) rank_kernel() {
    extern __shared__ unsigned long long sk[];
    const int tid = threadIdx.x;
    for (int k = tid; k < N; k += 256)
        sk[k] = ((unsigned long long)g_lab[k] << 45)
              | ((unsigned long long)fenc(g_x[k]) << 13)
              | (unsigned)k;
    __syncthreads();

    const int warp = tid >> 5, lane = tid & 31;
    const int row0 = (blockIdx.x * 8 + warp) * 8;
    unsigned long long mykey[8];
    int cnt[8];
#pragma unroll
    for (int r = 0; r < 8; r++) { mykey[r] = sk[row0 + r]; cnt[r] = 0; }

    for (int j = lane; j < N; j += 32) {
        const unsigned long long kj = sk[j];
#pragma unroll
        for (int r = 0; r < 8; r++) cnt[r] += (kj < mykey[r]) ? 1 : 0;
    }
#pragma unroll
    for (int r = 0; r < 8; r++)
#pragma unroll
        for (int o = 16; o; o >>= 1)
            cnt[r] += __shfl_xor_sync(0xffffffffu, cnt[r], o);

    if (lane < 8) {
        int gr = 0;
#pragma unroll
        for (int r = 0; r < 8; r++) if (lane == r) gr = cnt[r];
        const int row = row0 + lane;
        g_xs[gr] = g_x[row];
        g_As[gr] = g_A[row];
        g_Bs[gr] = g_B[row];
    }
}

// ---------------------------------------------------------------------------
// K3 build (1 x 1024, 64KB dyn smem): stage As/Bs floats in SMEM, then ff
// (compensated) per-label scans: PA = exclusive prefix of A, SB = suffix of B.
// All fp32-pipe; ff error ~1e-14 kills prefix-difference cancellation.
// ---------------------------------------------------------------------------
__global__ void __launch_bounds__(1024, 1) build_kernel() {
    extern __shared__ float sAB[];               // sA[0..N), sB[N..2N)
    float* sA = sAB;
    float* sB = sAB + N;
    __shared__ int s_off[11], s_cnt[10];
    const int tid = threadIdx.x;

    {   // coalesced stage
        float4* dA = (float4*)sA;
        float4* dB = (float4*)sB;
        const float4* gA = (const float4*)g_As;
        const float4* gB = (const float4*)g_Bs;
        for (int k = tid; k < N / 4; k += 1024) { dA[k] = gA[k]; dB[k] = gB[k]; }
    }
    if (tid == 0) {
        int acc = 0;
        for (int c = 0; c < 10; c++) {
            s_off[c] = acc; g_off[c] = acc;
            int cc = g_cnt[c]; s_cnt[c] = cc; acc += cc;
        }
        s_off[10] = acc; g_off[10] = acc;
    }
    __syncthreads();
    if (tid < 10 && s_cnt[tid] > 0) {
        g_mn[tid] = g_xs[s_off[tid]];
        g_mx[tid] = g_xs[s_off[tid] + s_cnt[tid] - 1];
    }

    const int w = tid >> 5, lane = tid & 31;
    if (w < 20) {
        const int c = w >> 1;
        const int off = s_off[c], L = s_cnt[c];
        const int base = off + c;                       // per-label extra slot
        const int chunk = (L + 31) >> 5;
        int st = lane * chunk; if (st > L) st = L;
        int en = st + chunk;   if (en > L) en = L;

        if ((w & 1) == 0) {
            // A: forward exclusive ff prefix
            ff s = {0.f, 0.f};
            for (int k = st; k < en; k++) s = ff_add_f(s, sA[off + k]);
            ff t = s;
#pragma unroll
            for (int o = 1; o < 32; o <<= 1) {
                ff v; v.h = __shfl_up_sync(~0u, t.h, o);
                      v.l = __shfl_up_sync(~0u, t.l, o);
                if (lane >= o) t = ff_add_ff(v, t);
            }
            ff neg; neg.h = -s.h; neg.l = -s.l;
            ff run = ff_add_ff(t, neg);                  // exclusive offset
            for (int k = st; k < en; k++) {
                g_PA[base + k] = make_float2(run.h, run.l);
                run = ff_add_f(run, sA[off + k]);
            }
            if (lane == 31) g_PA[base + L] = make_float2(run.h, run.l);
        } else {
            // B: suffix sums via reversed scan (accumulate small -> large)
            ff s = {0.f, 0.f};
            for (int r = st; r < en; r++) s = ff_add_f(s, sB[off + (L - 1 - r)]);
            ff t = s;
#pragma unroll
            for (int o = 1; o < 32; o <<= 1) {
                ff v; v.h = __shfl_up_sync(~0u, t.h, o);
                      v.l = __shfl_up_sync(~0u, t.l, o);
                if (lane >= o) t = ff_add_ff(v, t);
            }
            ff neg; neg.h = -s.h; neg.l = -s.l;
            ff run = ff_add_ff(t, neg);
            for (int r = st; r < en; r++) {
                run = ff_add_f(run, sB[off + (L - 1 - r)]);
                g_SB[base + (L - 1 - r)] = make_float2(run.h, run.l);
            }
            if (lane == 0) g_SB[base + L] = make_float2(0.f, 0.f);
        }
    }
}

// ---------------------------------------------------------------------------
// K4 query (256 x 320): R8 structure (fastest measured) with pure-fp32 window
// math. One thread per (row, label); scalar search state; xs in SMEM.
// ---------------------------------------------------------------------------
__global__ void __launch_bounds__(QT) query_kernel(float* __restrict__ out) {
    __shared__ float  sxs[N];                    // 32 KB
    __shared__ int    s_off[10], s_cnt[10];
    __shared__ float  s_mn[10], s_mx[10];
    __shared__ float  s_cand[QROWS][10];
    __shared__ float  s_v[QROWS][10];
    __shared__ float  s_loss[QROWS];
    __shared__ float  rls[8]; __shared__ int rpcs[8];
    __shared__ unsigned lastS;
    const int tid = threadIdx.x;
    {
        float4* dst = (float4*)sxs;
        const float4* src = (const float4*)g_xs;
        for (int k = tid; k < N / 4; k += QT) dst[k] = src[k];
    }
    if (tid < 10) {
        s_off[tid] = g_off[tid]; s_cnt[tid] = g_cnt[tid];
        s_mn[tid] = g_mn[tid];   s_mx[tid] = g_mx[tid];
    }
    __syncthreads();

    const int y = tid / 10, c = tid - y * 10;    // row-in-block, label
    const int i = blockIdx.x * QROWS + y;        // global row
    const float xi  = g_x[i];
    const int   lab = g_lab[i];
    const int   off = s_off[c], cnt = s_cnt[c];
    const bool  own = (c == lab);

    // m: first index in label-c segment with xs > xi
    int lo = 0, hi = cnt;
    for (int s = 0; s < 14; s++) {
        if (lo < hi) { int mid = (lo + hi) >> 1;
            if (sxs[off + mid] > xi) hi = mid; else lo = mid + 1; }
    }
    const int m = lo;

    // threshold candidate for this label
    float cand = 0.f;
    if (own) {
        lo = 0; hi = m;
        for (int s = 0; s < 14; s++) {
            if (lo < hi) { int mid = (lo + hi) >> 1;
                if (fabsf(xi - sxs[off + mid]) < 1.0f) hi = mid; else lo = mid + 1; }
        }
        const int a0 = lo;                       // a0 < m (self d=0)
        cand = fabsf(xi - sxs[off + a0]);
        lo = m; hi = cnt;
        for (int s = 0; s < 14; s++) {
            if (lo < hi) { int mid = (lo + hi) >> 1;
                if (fabsf(xi - sxs[off + mid]) < 1.0f) lo = mid + 1; else hi = mid; }
        }
        if (lo > m) cand = fmaxf(cand, fabsf(xi - sxs[off + lo - 1]));
    } else if (cnt > 0) {
        cand = fmaxf(fabsf(xi - s_mn[c]), fabsf(xi - s_mx[c]));
    }
    s_cand[y][c] = cand;
    __syncthreads();

    float th = s_cand[y][0];
#pragma unroll
    for (int k = 1; k < 10; k++) th = fmaxf(th, s_cand[y][k]);
    const float pm = fminf(1.0f, th);
    const float bd = own ? pm : th;

    // aa: first in [0,m) with d<bd ; bb: first in [m,cnt) with d>=bd
    lo = 0; hi = m;
    for (int s = 0; s < 14; s++) {
        if (lo < hi) { int mid = (lo + hi) >> 1;
            if (fabsf(xi - sxs[off + mid]) < bd) hi = mid; else lo = mid + 1; }
    }
    const int aa = lo;
    lo = m; hi = cnt;
    for (int s = 0; s < 14; s++) {
        if (lo < hi) { int mid = (lo + hi) >> 1;
            if (fabsf(xi - sxs[off + mid]) < bd) lo = mid + 1; else hi = mid; }
    }
    const int bb = lo;

    {   // e = Bi*(sum A over [aa,m)) + Ai*(sum B over [m,bb)), ff-compensated
        const float Ai = g_A[i], Bi = g_B[i];
        const int e = off + c;
        float2 Pm = g_PA[e + m],  Paa = g_PA[e + aa];
        float2 Sm = g_SB[e + m],  Sbb = g_SB[e + bb];
        float left  = (Pm.x - Paa.x) + (Pm.y - Paa.y);
        float right = (Sm.x - Sbb.x) + (Sm.y - Sbb.y);
        s_v[y][c] = Bi * left + Ai * right;
    }
    __syncthreads();

    if (c == 0) {
        float pos = s_v[y][lab], neg = 0.f;
#pragma unroll
        for (int k = 0; k < 10; k++) if (k != lab) neg += s_v[y][k];
        float loss = 0.f;
        if (th > 0.f && pos > 0.f)
            loss = logf((pos + fmaxf(neg, 0.f)) / pos);
        s_loss[y] = loss;
    }
    __syncthreads();

    if (tid < 32) {
        float l = s_loss[tid];
        int   p = (l < 0.6f) ? 1 : 0;
#pragma unroll
        for (int o = 16; o; o >>= 1) {
            l += __shfl_xor_sync(~0u, l, o);
            p += __shfl_xor_sync(~0u, p, o);
        }
        if (tid == 0) {
            g_pls[blockIdx.x] = l;
            g_ppc[blockIdx.x] = p;
            __threadfence();
            lastS = atomicAdd(&g_ticket, 1u);
        }
    }
    __syncthreads();
    if (lastS == QB - 1) {                        // last block finalizes
        __threadfence();
        if (tid < QB) {
            float v = g_pls[tid]; int p = g_ppc[tid];
#pragma unroll
            for (int o = 16; o; o >>= 1) {
                v += __shfl_xor_sync(~0u, v, o);
                p += __shfl_xor_sync(~0u, p, o);
            }
            if ((tid & 31) == 0) { rls[tid >> 5] = v; rpcs[tid >> 5] = p; }
        }
        __syncthreads();
        if (tid == 0) {
            float fs = 0.f; int fc = 0;
            for (int k = 0; k < 8; k++) { fs += rls[k]; fc += rpcs[k]; }
            out[0] = fs / (float)N;
            out[1] = (float)fc / (float)N;
            out[2] = ((float)g_ps / FIXP) / (float)g_pc;
            out[3] = ((float)g_ns / FIXP) / (float)g_nc;
            for (int k = 0; k < 10; k++) g_cnt[k] = 0;   // reset for replay
            g_ps = 0ull; g_ns = 0ull; g_pc = 0u; g_nc = 0u;
            g_ticket = 0u;
        }
    }
}

// ---------------------------------------------------------------------------
extern "C" void kernel_launch(void* const* d_in, const int* in_sizes, int n_in,
                              void* d_out, int out_size) {
    const float* x   = (const float*)d_in[0];
    const int*   t32 = (const int*)d_in[1];
    float*       out = (float*)d_out;

    cudaFuncSetAttribute(rank_kernel,
                         cudaFuncAttributeMaxDynamicSharedMemorySize, 65536);
    cudaFuncSetAttribute(build_kernel,
                         cudaFuncAttributeMaxDynamicSharedMemorySize, 65536);

    prep_kernel<<<32, 256>>>(x, t32);
    rank_kernel<<<128, 256, 65536>>>();
    build_kernel<<<1, 1024, 65536>>>();
    query_kernel<<<QB, QT>>>(out);
}

// round 12
// speedup vs baseline: 2.4353x; 1.3000x over previous
#include <cuda_runtime.h>
#include <math.h>

#define N       8192
#define FIXP    4194304.0f      // 2^22 fixed point for last-row stats
#define QB      128             // query blocks (1 wave on 148 SMs)
#define QT      640             // 64 rows x 10 labels
#define QROWS   64
#define LMAX    1024            // per-label bucket capacity (L ~ 820 +- 28)

// ---- float-float (Dekker two-sum) helpers ---------------------------------
struct ff { float h, l; };
__device__ __forceinline__ ff ff_add_f(ff x, float a) {
    float s  = x.h + a;
    float bv = s - x.h;
    float e  = (x.h - (s - bv)) + (a - bv);
    float l2 = x.l + e;
    float t  = s + l2;
    ff r; r.h = t; r.l = l2 - (t - s); return r;
}
__device__ __forceinline__ ff ff_add_ff(ff x, ff y) {
    float s  = x.h + y.h;
    float bv = s - x.h;
    float e  = (x.h - (s - bv)) + (y.h - bv) + x.l + y.l;
    float t  = s + e;
    ff r; r.h = t; r.l = e - (t - s); return r;
}

// ---- device globals -------------------------------------------------------
__device__ float              g_x[N];
__device__ unsigned char      g_lab[N];
__device__ float              g_A[N], g_B[N];    // expf(+-16x), original order
__device__ unsigned long long g_tmp[10 * LMAX];  // per-label unordered keys
__device__ int                g_cnt[10];
__device__ int                g_off[11];
__device__ float              g_mn[10], g_mx[10];
__device__ float              g_xs[N];           // sorted by (label, x, idx)
__device__ float              g_As[N], g_Bs[N];
__device__ float2             g_PA[N + 16];      // per-label EXCLUSIVE ff prefix of A
__device__ float2             g_SB[N + 16];      // per-label ff SUFFIX sums of B
__device__ float              g_pls[QB];
__device__ int                g_ppc[QB];
__device__ unsigned long long g_ps = 0ull, g_ns = 0ull;
__device__ unsigned g_pc = 0u, g_nc = 0u;
__device__ unsigned g_ticket = 0u;

__device__ __forceinline__ unsigned fenc(float f) {    // order-preserving key
    unsigned u = __float_as_uint(f);
    return (u & 0x80000000u) ? ~u : (u | 0x80000000u);
}
__device__ __forceinline__ float fdec(unsigned k) {
    return __uint_as_float((k & 0x80000000u) ? (k & 0x7FFFFFFFu) : ~k);
}

// ---------------------------------------------------------------------------
// K1 prep (32 x 256): dtype-layout detect (JAX demotes int64->int32; odd words
// of first 16KB zero iff true int64), decode, exp tables, scatter key into
// per-label bucket (slot via atomic; order irrelevant, rank fixes it),
// last-row stats (deterministic fixed-point atomics).
// ---------------------------------------------------------------------------
__global__ void __launch_bounds__(256) prep_kernel(const float* __restrict__ x,
                                                   const int* __restrict__ t32) {
    __shared__ int flag;
    __shared__ unsigned long long rps[8], rns[8];
    __shared__ int rpc[8], rnc[8];
    const int tid = threadIdx.x;
    if (tid == 0) flag = 0;
    __syncthreads();
    for (int k = tid; k < 2048; k += 256)
        if (t32[2 * k + 1] != 0) atomicOr(&flag, 1);
    __syncthreads();
    const int is32 = flag;

    const int i = blockIdx.x * 256 + tid;
    const float xi = x[i];
    const int lbl = is32 ? t32[i] : t32[2 * i];
    g_x[i] = xi;
    g_lab[i] = (unsigned char)lbl;
    g_A[i] = expf(16.0f * xi);
    g_B[i] = expf(-16.0f * xi);
    const int slot = atomicAdd(&g_cnt[lbl], 1);
    g_tmp[lbl * LMAX + slot] =
        ((unsigned long long)fenc(xi) << 13) | (unsigned)i;   // idx tiebreak

    const float xl = x[N - 1];
    const int   ll = is32 ? t32[N - 1] : t32[2 * (N - 1)];
    float d = fabsf(xl - xi);
    unsigned long long pq = 0ull, nq = 0ull; int pc = 0, nc = 0;
    if (lbl == ll) { if (d < 1.0f) { pq = (unsigned long long)(d * FIXP + 0.5f); pc = 1; } }
    else           { nq = (unsigned long long)(d * FIXP + 0.5f); nc = 1; }
#pragma unroll
    for (int o = 16; o; o >>= 1) {
        pq += __shfl_xor_sync(~0u, pq, o); nq += __shfl_xor_sync(~0u, nq, o);
        pc += __shfl_xor_sync(~0u, pc, o); nc += __shfl_xor_sync(~0u, nc, o);
    }
    const int w = tid >> 5, l = tid & 31;
    if (l == 0) { rps[w] = pq; rns[w] = nq; rpc[w] = pc; rnc[w] = nc; }
    __syncthreads();
    if (tid == 0) {
        unsigned long long sp = 0ull, sn = 0ull; int cp = 0, cn = 0;
        for (int k = 0; k < 8; k++) { sp += rps[k]; sn += rns[k]; cp += rpc[k]; cn += rnc[k]; }
        atomicAdd(&g_ps, sp); atomicAdd(&g_ns, sn);
        atomicAdd(&g_pc, (unsigned)cp); atomicAdd(&g_nc, (unsigned)cn);
    }
}

// ---------------------------------------------------------------------------
// K2 rank2 (640 x 128): per-label counting rank. block = (label c, chunk of 16
// rows). Segment keys staged in 8KB smem, padded to LMAX with +inf keys so the
// count loop is a branchless fixed 32 iterations. ~6.7M compares total (10x
// fewer than full-order ranking). Scatter x / expf tables to sorted arrays.
// ---------------------------------------------------------------------------
__global__ void __launch_bounds__(128) rank2_kernel() {
    __shared__ unsigned long long sk[LMAX];
    __shared__ int s_base, s_L;
    const int tid = threadIdx.x;
    const int c = blockIdx.x >> 6;          // label
    const int chunk = blockIdx.x & 63;      // 16 rows per chunk

    if (tid == 0) {
        int base = 0;
        for (int k = 0; k < c; k++) base += g_cnt[k];
        s_base = base; s_L = g_cnt[c];
    }
    __syncthreads();
    const int L = s_L, base = s_base;
    for (int k = tid; k < LMAX; k += 128)
        sk[k] = (k < L) ? g_tmp[c * LMAX + k] : ~0ull;
    __syncthreads();

    const int warp = tid >> 5, lane = tid & 31;
    const int r0 = chunk * 16 + warp * 4;
    if (r0 >= L) return;

    unsigned long long kr[4]; int cnt[4];
#pragma unroll
    for (int r = 0; r < 4; r++) {
        kr[r] = (r0 + r < L) ? sk[r0 + r] : ~0ull;
        cnt[r] = 0;
    }
#pragma unroll 4
    for (int j = lane; j < LMAX; j += 32) {
        const unsigned long long kj = sk[j];
#pragma unroll
        for (int r = 0; r < 4; r++) cnt[r] += (kj < kr[r]) ? 1 : 0;
    }
#pragma unroll
    for (int r = 0; r < 4; r++)
#pragma unroll
        for (int o = 16; o; o >>= 1)
            cnt[r] += __shfl_xor_sync(0xffffffffu, cnt[r], o);

    if (lane < 4 && r0 + lane < L) {
        int gr = 0;
#pragma unroll
        for (int r = 0; r < 4; r++) if (lane == r) gr = cnt[r];
        const unsigned long long key = sk[r0 + lane];
        const float xv = fdec((unsigned)(key >> 13));
        g_xs[base + gr] = xv;
        g_As[base + gr] = expf(16.0f * xv);
        g_Bs[base + gr] = expf(-16.0f * xv);
    }
}

// ---------------------------------------------------------------------------
// K3 build (1 x 1024, 64KB dyn smem): stage As/Bs in SMEM, then ff-compensated
// per-label scans: PA = exclusive prefix of A, SB = suffix sums of B.
// ---------------------------------------------------------------------------
__global__ void __launch_bounds__(1024, 1) build_kernel() {
    extern __shared__ float sAB[];               // sA[0..N), sB[N..2N)
    float* sA = sAB;
    float* sB = sAB + N;
    __shared__ int s_off[11], s_cnt[10];
    const int tid = threadIdx.x;

    {
        float4* dA = (float4*)sA;
        float4* dB = (float4*)sB;
        const float4* gA = (const float4*)g_As;
        const float4* gB = (const float4*)g_Bs;
        for (int k = tid; k < N / 4; k += 1024) { dA[k] = gA[k]; dB[k] = gB[k]; }
    }
    if (tid == 0) {
        int acc = 0;
        for (int c = 0; c < 10; c++) {
            s_off[c] = acc; g_off[c] = acc;
            int cc = g_cnt[c]; s_cnt[c] = cc; acc += cc;
        }
        s_off[10] = acc; g_off[10] = acc;
    }
    __syncthreads();
    if (tid < 10 && s_cnt[tid] > 0) {
        g_mn[tid] = g_xs[s_off[tid]];
        g_mx[tid] = g_xs[s_off[tid] + s_cnt[tid] - 1];
    }

    const int w = tid >> 5, lane = tid & 31;
    if (w < 20) {
        const int c = w >> 1;
        const int off = s_off[c], L = s_cnt[c];
        const int base = off + c;                       // per-label extra slot
        const int chunk = (L + 31) >> 5;
        int st = lane * chunk; if (st > L) st = L;
        int en = st + chunk;   if (en > L) en = L;

        if ((w & 1) == 0) {
            ff s = {0.f, 0.f};
            for (int k = st; k < en; k++) s = ff_add_f(s, sA[off + k]);
            ff t = s;
#pragma unroll
            for (int o = 1; o < 32; o <<= 1) {
                ff v; v.h = __shfl_up_sync(~0u, t.h, o);
                      v.l = __shfl_up_sync(~0u, t.l, o);
                if (lane >= o) t = ff_add_ff(v, t);
            }
            ff neg; neg.h = -s.h; neg.l = -s.l;
            ff run = ff_add_ff(t, neg);
            for (int k = st; k < en; k++) {
                g_PA[base + k] = make_float2(run.h, run.l);
                run = ff_add_f(run, sA[off + k]);
            }
            if (lane == 31) g_PA[base + L] = make_float2(run.h, run.l);
        } else {
            ff s = {0.f, 0.f};
            for (int r = st; r < en; r++) s = ff_add_f(s, sB[off + (L - 1 - r)]);
            ff t = s;
#pragma unroll
            for (int o = 1; o < 32; o <<= 1) {
                ff v; v.h = __shfl_up_sync(~0u, t.h, o);
                      v.l = __shfl_up_sync(~0u, t.l, o);
                if (lane >= o) t = ff_add_ff(v, t);
            }
            ff neg; neg.h = -s.h; neg.l = -s.l;
            ff run = ff_add_ff(t, neg);
            for (int r = st; r < en; r++) {
                run = ff_add_f(run, sB[off + (L - 1 - r)]);
                g_SB[base + (L - 1 - r)] = make_float2(run.h, run.l);
            }
            if (lane == 0) g_SB[base + L] = make_float2(0.f, 0.f);
        }
    }
}

// ---------------------------------------------------------------------------
// K4 query (128 x 640, 1 wave): thread = (row y, label c), R8 structure.
// xs in SMEM; scalar binary-search state; ff window sums; ticket finalize.
// ---------------------------------------------------------------------------
__global__ void __launch_bounds__(QT) query_kernel(float* __restrict__ out) {
    __shared__ float  sxs[N];                    // 32 KB
    __shared__ int    s_off[10], s_cnt[10];
    __shared__ float  s_mn[10], s_mx[10];
    __shared__ float  s_cand[QROWS][10];
    __shared__ float  s_v[QROWS][10];
    __shared__ float  s_loss[QROWS];
    __shared__ float  rls[4]; __shared__ int rpcs[4];
    __shared__ unsigned lastS;
    const int tid = threadIdx.x;
    {
        float4* dst = (float4*)sxs;
        const float4* src = (const float4*)g_xs;
        for (int k = tid; k < N / 4; k += QT) dst[k] = src[k];
    }
    if (tid < 10) {
        s_off[tid] = g_off[tid]; s_cnt[tid] = g_cnt[tid];
        s_mn[tid] = g_mn[tid];   s_mx[tid] = g_mx[tid];
    }
    __syncthreads();

    const int y = tid / 10, c = tid - y * 10;    // row-in-block, label
    const int i = blockIdx.x * QROWS + y;        // global row
    const float xi  = g_x[i];
    const int   lab = g_lab[i];
    const int   off = s_off[c], cnt = s_cnt[c];
    const bool  own = (c == lab);

    // m: first index in label-c segment with xs > xi
    int lo = 0, hi = cnt;
    for (int s = 0; s < 14; s++) {
        if (lo < hi) { int mid = (lo + hi) >> 1;
            if (sxs[off + mid] > xi) hi = mid; else lo = mid + 1; }
    }
    const int m = lo;

    // threshold candidate for this label
    float cand = 0.f;
    if (own) {
        lo = 0; hi = m;
        for (int s = 0; s < 14; s++) {
            if (lo < hi) { int mid = (lo + hi) >> 1;
                if (fabsf(xi - sxs[off + mid]) < 1.0f) hi = mid; else lo = mid + 1; }
        }
        const int a0 = lo;                       // a0 < m (self d=0)
        cand = fabsf(xi - sxs[off + a0]);
        lo = m; hi = cnt;
        for (int s = 0; s < 14; s++) {
            if (lo < hi) { int mid = (lo + hi) >> 1;
                if (fabsf(xi - sxs[off + mid]) < 1.0f) lo = mid + 1; else hi = mid; }
        }
        if (lo > m) cand = fmaxf(cand, fabsf(xi - sxs[off + lo - 1]));
    } else if (cnt > 0) {
        cand = fmaxf(fabsf(xi - s_mn[c]), fabsf(xi - s_mx[c]));
    }
    s_cand[y][c] = cand;
    __syncthreads();

    float th = s_cand[y][0];
#pragma unroll
    for (int k = 1; k < 10; k++) th = fmaxf(th, s_cand[y][k]);
    const float pm = fminf(1.0f, th);
    const float bd = own ? pm : th;

    // aa: first in [0,m) with d<bd ; bb: first in [m,cnt) with d>=bd
    lo = 0; hi = m;
    for (int s = 0; s < 14; s++) {
        if (lo < hi) { int mid = (lo + hi) >> 1;
            if (fabsf(xi - sxs[off + mid]) < bd) hi = mid; else lo = mid + 1; }
    }
    const int aa = lo;
    lo = m; hi = cnt;
    for (int s = 0; s < 14; s++) {
        if (lo < hi) { int mid = (lo + hi) >> 1;
            if (fabsf(xi - sxs[off + mid]) < bd) lo = mid + 1; else hi = mid; }
    }
    const int bb = lo;

    {   // e = Bi*(sum A over [aa,m)) + Ai*(sum B over [m,bb)), ff-compensated
        const float Ai = g_A[i], Bi = g_B[i];
        const int e = off + c;
        float2 Pm = g_PA[e + m],  Paa = g_PA[e + aa];
        float2 Sm = g_SB[e + m],  Sbb = g_SB[e + bb];
        float left  = (Pm.x - Paa.x) + (Pm.y - Paa.y);
        float right = (Sm.x - Sbb.x) + (Sm.y - Sbb.y);
        s_v[y][c] = Bi * left + Ai * right;
    }
    __syncthreads();

    if (c == 0) {
        float pos = s_v[y][lab], neg = 0.f;
#pragma unroll
        for (int k = 0; k < 10; k++) if (k != lab) neg += s_v[y][k];
        float loss = 0.f;
        if (th > 0.f && pos > 0.f)
            loss = logf((pos + fmaxf(neg, 0.f)) / pos);
        s_loss[y] = loss;
    }
    __syncthreads();

    if (tid < QROWS) {                           // 2 warps reduce 64 rows
        float l = s_loss[tid];
        int   p = (l < 0.6f) ? 1 : 0;
#pragma unroll
        for (int o = 16; o; o >>= 1) {
            l += __shfl_xor_sync(~0u, l, o);
            p += __shfl_xor_sync(~0u, p, o);
        }
        if ((tid & 31) == 0) { rls[tid >> 5] = l; rpcs[tid >> 5] = p; }
    }
    __syncthreads();
    if (tid == 0) {
        g_pls[blockIdx.x] = rls[0] + rls[1];
        g_ppc[blockIdx.x] = rpcs[0] + rpcs[1];
        __threadfence();
        lastS = atomicAdd(&g_ticket, 1u);
    }
    __syncthreads();
    if (lastS == QB - 1) {                       // last block finalizes
        __threadfence();
        if (tid < QB) {
            float v = g_pls[tid]; int p = g_ppc[tid];
#pragma unroll
            for (int o = 16; o; o >>= 1) {
                v += __shfl_xor_sync(~0u, v, o);
                p += __shfl_xor_sync(~0u, p, o);
            }
            if ((tid & 31) == 0) { rls[tid >> 5] = v; rpcs[tid >> 5] = p; }
        }
        __syncthreads();
        if (tid == 0) {
            float fs = rls[0] + rls[1] + rls[2] + rls[3];
            int   fc = rpcs[0] + rpcs[1] + rpcs[2] + rpcs[3];
            out[0] = fs / (float)N;
            out[1] = (float)fc / (float)N;
            out[2] = ((float)g_ps / FIXP) / (float)g_pc;
            out[3] = ((float)g_ns / FIXP) / (float)g_nc;
            for (int k = 0; k < 10; k++) g_cnt[k] = 0;   // reset for replay
            g_ps = 0ull; g_ns = 0ull; g_pc = 0u; g_nc = 0u;
            g_ticket = 0u;
        }
    }
}

// ---------------------------------------------------------------------------
extern "C" void kernel_launch(void* const* d_in, const int* in_sizes, int n_in,
                              void* d_out, int out_size) {
    const float* x   = (const float*)d_in[0];
    const int*   t32 = (const int*)d_in[1];
    float*       out = (float*)d_out;

    cudaFuncSetAttribute(build_kernel,
                         cudaFuncAttributeMaxDynamicSharedMemorySize, 65536);

    prep_kernel<<<32, 256>>>(x, t32);
    rank2_kernel<<<640, 128>>>();
    build_kernel<<<1, 1024, 65536>>>();
    query_kernel<<<QB, QT>>>(out);
}

// round 13
// speedup vs baseline: 3.1706x; 1.3019x over previous
#include <cuda_runtime.h>
#include <math.h>

#define N       8192
#define FIXP    4194304.0f      // 2^22 fixed point for last-row stats
#define GRID    128             // all blocks resident (<=148 SMs) -> spin barrier safe
#define THREADS 640             // 64 rows x 10 labels in query phase
#define QROWS   64
#define LMAX    1024            // per-label bucket capacity (L ~ 820 +- 28)
#define NSTEP   11              // binary search steps: ranges <= 1024

// ---- float-float (Dekker two-sum) helpers ---------------------------------
struct ff { float h, l; };
__device__ __forceinline__ ff ff_add_f(ff x, float a) {
    float s  = x.h + a;
    float bv = s - x.h;
    float e  = (x.h - (s - bv)) + (a - bv);
    float l2 = x.l + e;
    float t  = s + l2;
    ff r; r.h = t; r.l = l2 - (t - s); return r;
}
__device__ __forceinline__ ff ff_add_ff(ff x, ff y) {
    float s  = x.h + y.h;
    float bv = s - x.h;
    float e  = (x.h - (s - bv)) + (y.h - bv) + x.l + y.l;
    float t  = s + e;
    ff r; r.h = t; r.l = e - (t - s); return r;
}

// ---- device globals -------------------------------------------------------
__device__ float              g_x[N];
__device__ unsigned char      g_lab[N];
__device__ float              g_A[N], g_B[N];    // expf(+-16x), original order
__device__ unsigned long long g_tmp[10 * LMAX];  // per-label unordered keys
__device__ int                g_cnt[10];
__device__ float              g_xs[N];           // sorted by (label, x, idx)
__device__ float              g_As[N], g_Bs[N];
__device__ float2             g_PA[N + 16];      // per-label EXCLUSIVE ff prefix of A
__device__ float2             g_SB[N + 16];      // per-label ff SUFFIX sums of B
__device__ float              g_pls[GRID];
__device__ int                g_ppc[GRID];
__device__ unsigned long long g_ps = 0ull, g_ns = 0ull;
__device__ unsigned g_pc = 0u, g_nc = 0u;
__device__ unsigned g_ticket = 0u;
__device__ unsigned g_bar = 0u;                  // grid barrier counter

__device__ __forceinline__ unsigned fenc(float f) {    // order-preserving key
    unsigned u = __float_as_uint(f);
    return (u & 0x80000000u) ? ~u : (u | 0x80000000u);
}
__device__ __forceinline__ float fdec(unsigned k) {
    return __uint_as_float((k & 0x80000000u) ? (k & 0x7FFFFFFFu) : ~k);
}

// All GRID blocks resident (1 block/SM, GRID <= 148) -> spin is deadlock-free.
__device__ __forceinline__ void grid_barrier(unsigned target) {
    __syncthreads();
    if (threadIdx.x == 0) {
        __threadfence();
        atomicAdd(&g_bar, 1u);
        while (atomicAdd(&g_bar, 0u) < target) { }
        __threadfence();
    }
    __syncthreads();
}

// ---------------------------------------------------------------------------
// Fused kernel: prep -> rank -> build -> query in one launch (3 grid barriers)
// ---------------------------------------------------------------------------
__global__ void __launch_bounds__(THREADS, 1)
fused_kernel(const float* __restrict__ x, const int* __restrict__ t32,
             float* __restrict__ out) {
    __shared__ __align__(16) unsigned char s_buf[32768];  // keys / scan stage / sxs
    __shared__ int   s_off[11], s_scnt[10];
    __shared__ float s_cand[QROWS][10];
    __shared__ float s_v[QROWS][10];
    __shared__ float s_loss[QROWS];
    __shared__ float rls[4]; __shared__ int rpcs[4];
    __shared__ unsigned lastS;
    __shared__ int s_flag;
    const int tid = threadIdx.x;
    const int bid = blockIdx.x;

    // ===== phase 1: prep (block owns elements [64*bid, 64*bid+64) == its query rows)
    if (tid == 0) s_flag = 0;
    __syncthreads();
    // dtype-layout detect: JAX demotes int64->int32; odd words of first 16KB
    // are zero iff buffer is true int64.
    for (int k = tid; k < 2048; k += THREADS)
        if (t32[2 * k + 1] != 0) atomicOr(&s_flag, 1);
    __syncthreads();
    const int is32 = s_flag;

    if (tid < 64) {
        const int i = bid * 64 + tid;
        const float xi = x[i];
        const int lbl = is32 ? t32[i] : t32[2 * i];      // int64 LE lo word
        g_x[i] = xi;
        g_lab[i] = (unsigned char)lbl;
        g_A[i] = expf(16.0f * xi);
        g_B[i] = expf(-16.0f * xi);
        const int slot = atomicAdd(&g_cnt[lbl], 1);
        g_tmp[lbl * LMAX + slot] =
            ((unsigned long long)fenc(xi) << 13) | (unsigned)i;  // idx tiebreak

        // last-row stats, fixed point (deterministic across order)
        const float xl = x[N - 1];
        const int   ll = is32 ? t32[N - 1] : t32[2 * (N - 1)];
        float d = fabsf(xl - xi);
        unsigned long long pq = 0ull, nq = 0ull; int pc = 0, nc = 0;
        if (lbl == ll) { if (d < 1.0f) { pq = (unsigned long long)(d * FIXP + 0.5f); pc = 1; } }
        else           { nq = (unsigned long long)(d * FIXP + 0.5f); nc = 1; }
#pragma unroll
        for (int o = 16; o; o >>= 1) {
            pq += __shfl_xor_sync(~0u, pq, o); nq += __shfl_xor_sync(~0u, nq, o);
            pc += __shfl_xor_sync(~0u, pc, o); nc += __shfl_xor_sync(~0u, nc, o);
        }
        if ((tid & 31) == 0) {
            atomicAdd(&g_ps, pq); atomicAdd(&g_ns, nq);
            atomicAdd(&g_pc, (unsigned)pc); atomicAdd(&g_nc, (unsigned)nc);
        }
    }
    grid_barrier(GRID);

    // label offsets (local per block, from final g_cnt)
    if (tid == 0) {
        int acc = 0;
        for (int c = 0; c < 10; c++) { s_off[c] = acc; int cc = g_cnt[c]; s_scnt[c] = cc; acc += cc; }
        s_off[10] = acc;
    }
    __syncthreads();

    // ===== phase 2: per-label counting rank. task t = (label t%10, 80-row chunk t/10)
    {
        unsigned long long* sk = (unsigned long long*)s_buf;   // 8KB
        for (int t = bid; t < 130; t += GRID) {
            const int c = t % 10, chunk = t / 10;
            const int L = s_scnt[c], base = s_off[c];
            for (int k = tid; k < LMAX; k += THREADS)
                sk[k] = (k < L) ? g_tmp[c * LMAX + k] : ~0ull;
            __syncthreads();
            const int warp = tid >> 5, lane = tid & 31;
            const int r0 = chunk * 80 + warp * 4;
            if (r0 < L) {
                unsigned long long kr[4]; int cnt[4];
#pragma unroll
                for (int r = 0; r < 4; r++) {
                    kr[r] = (r0 + r < L) ? sk[r0 + r] : ~0ull;
                    cnt[r] = 0;
                }
#pragma unroll 4
                for (int j = lane; j < LMAX; j += 32) {
                    const unsigned long long kj = sk[j];
#pragma unroll
                    for (int r = 0; r < 4; r++) cnt[r] += (kj < kr[r]) ? 1 : 0;
                }
#pragma unroll
                for (int r = 0; r < 4; r++)
#pragma unroll
                    for (int o = 16; o; o >>= 1)
                        cnt[r] += __shfl_xor_sync(0xffffffffu, cnt[r], o);
                if (lane < 4 && r0 + lane < L) {
                    int gr = 0;
#pragma unroll
                    for (int r = 0; r < 4; r++) if (lane == r) gr = cnt[r];
                    const unsigned long long key = sk[r0 + lane];
                    const float xv = fdec((unsigned)(key >> 13));
                    g_xs[base + gr] = xv;
                    g_As[base + gr] = expf(16.0f * xv);
                    g_Bs[base + gr] = expf(-16.0f * xv);
                }
            }
            __syncthreads();
        }
    }
    grid_barrier(2 * GRID);

    // ===== phase 3: ff prefix/suffix scans, block c < 10 handles label c
    if (bid < 10) {
        const int c = bid;
        float* sA = (float*)s_buf;          // L floats
        float* sB = sA + LMAX;              // L floats
        const int off = s_off[c], L = s_scnt[c];
        const int base = off + c;           // per-label extra slot
        for (int k = tid; k < L; k += THREADS) { sA[k] = g_As[off + k]; sB[k] = g_Bs[off + k]; }
        __syncthreads();
        const int w = tid >> 5, lane = tid & 31;
        const int chunk = (L + 31) >> 5;
        int st = lane * chunk; if (st > L) st = L;
        int en = st + chunk;   if (en > L) en = L;
        if (w == 0) {
            // A: forward exclusive ff prefix (ascending terms)
            ff s = {0.f, 0.f};
            for (int k = st; k < en; k++) s = ff_add_f(s, sA[k]);
            ff t = s;
#pragma unroll
            for (int o = 1; o < 32; o <<= 1) {
                ff v; v.h = __shfl_up_sync(~0u, t.h, o);
                      v.l = __shfl_up_sync(~0u, t.l, o);
                if (lane >= o) t = ff_add_ff(v, t);
            }
            ff neg; neg.h = -s.h; neg.l = -s.l;
            ff run = ff_add_ff(t, neg);
            for (int k = st; k < en; k++) {
                g_PA[base + k] = make_float2(run.h, run.l);
                run = ff_add_f(run, sA[k]);
            }
            if (lane == 31) g_PA[base + L] = make_float2(run.h, run.l);
        } else if (w == 1) {
            // B: suffix sums via reversed scan (accumulate small -> large)
            ff s = {0.f, 0.f};
            for (int r = st; r < en; r++) s = ff_add_f(s, sB[L - 1 - r]);
            ff t = s;
#pragma unroll
            for (int o = 1; o < 32; o <<= 1) {
                ff v; v.h = __shfl_up_sync(~0u, t.h, o);
                      v.l = __shfl_up_sync(~0u, t.l, o);
                if (lane >= o) t = ff_add_ff(v, t);
            }
            ff neg; neg.h = -s.h; neg.l = -s.l;
            ff run = ff_add_ff(t, neg);
            for (int r = st; r < en; r++) {
                run = ff_add_f(run, sB[L - 1 - r]);
                g_SB[base + (L - 1 - r)] = make_float2(run.h, run.l);
            }
            if (lane == 0) g_SB[base + L] = make_float2(0.f, 0.f);
        }
    }
    grid_barrier(3 * GRID);

    // ===== phase 4: query (thread = (row y, label c)); bit-identical R12 math
    float* sxs = (float*)s_buf;             // 32KB sorted xs
    {
        float4* dst = (float4*)sxs;
        const float4* src = (const float4*)g_xs;
        for (int k = tid; k < N / 4; k += THREADS) dst[k] = src[k];
    }
    __syncthreads();

    const int y = tid / 10, c = tid - y * 10;
    const int i = bid * QROWS + y;
    const float xi  = g_x[i];
    const int   lab = g_lab[i];
    const int   off = s_off[c], cnt = s_scnt[c];
    const bool  own = (c == lab);

    // m: first index in label-c segment with xs > xi
    int lo = 0, hi = cnt;
    for (int s = 0; s < NSTEP; s++) {
        if (lo < hi) { int mid = (lo + hi) >> 1;
            if (sxs[off + mid] > xi) hi = mid; else lo = mid + 1; }
    }
    const int m = lo;

    // threshold candidate for this label
    float cand = 0.f;
    if (own) {
        lo = 0; hi = m;
        for (int s = 0; s < NSTEP; s++) {
            if (lo < hi) { int mid = (lo + hi) >> 1;
                if (fabsf(xi - sxs[off + mid]) < 1.0f) hi = mid; else lo = mid + 1; }
        }
        const int a0 = lo;                   // a0 < m (self d=0)
        cand = fabsf(xi - sxs[off + a0]);
        lo = m; hi = cnt;
        for (int s = 0; s < NSTEP; s++) {
            if (lo < hi) { int mid = (lo + hi) >> 1;
                if (fabsf(xi - sxs[off + mid]) < 1.0f) lo = mid + 1; else hi = mid; }
        }
        if (lo > m) cand = fmaxf(cand, fabsf(xi - sxs[off + lo - 1]));
    } else if (cnt > 0) {
        cand = fmaxf(fabsf(xi - sxs[off]), fabsf(xi - sxs[off + cnt - 1]));
    }
    s_cand[y][c] = cand;
    __syncthreads();

    float th = s_cand[y][0];
#pragma unroll
    for (int k = 1; k < 10; k++) th = fmaxf(th, s_cand[y][k]);
    const float pm = fminf(1.0f, th);
    const float bd = own ? pm : th;

    // aa: first in [0,m) with d<bd ; bb: first in [m,cnt) with d>=bd
    lo = 0; hi = m;
    for (int s = 0; s < NSTEP; s++) {
        if (lo < hi) { int mid = (lo + hi) >> 1;
            if (fabsf(xi - sxs[off + mid]) < bd) hi = mid; else lo = mid + 1; }
    }
    const int aa = lo;
    lo = m; hi = cnt;
    for (int s = 0; s < NSTEP; s++) {
        if (lo < hi) { int mid = (lo + hi) >> 1;
            if (fabsf(xi - sxs[off + mid]) < bd) lo = mid + 1; else hi = mid; }
    }
    const int bb = lo;

    {   // e = Bi*(sum A over [aa,m)) + Ai*(sum B over [m,bb)), ff-compensated
        const float Ai = g_A[i], Bi = g_B[i];
        const int e = off + c;
        float2 Pm = g_PA[e + m],  Paa = g_PA[e + aa];
        float2 Sm = g_SB[e + m],  Sbb = g_SB[e + bb];
        float left  = (Pm.x - Paa.x) + (Pm.y - Paa.y);
        float right = (Sm.x - Sbb.x) + (Sm.y - Sbb.y);
        s_v[y][c] = Bi * left + Ai * right;
    }
    __syncthreads();

    if (c == 0) {
        float pos = s_v[y][lab], neg = 0.f;
#pragma unroll
        for (int k = 0; k < 10; k++) if (k != lab) neg += s_v[y][k];
        float loss = 0.f;
        if (th > 0.f && pos > 0.f)
            loss = logf((pos + fmaxf(neg, 0.f)) / pos);
        s_loss[y] = loss;
    }
    __syncthreads();

    if (tid < QROWS) {                       // 2 warps reduce 64 rows
        float l = s_loss[tid];
        int   p = (l < 0.6f) ? 1 : 0;
#pragma unroll
        for (int o = 16; o; o >>= 1) {
            l += __shfl_xor_sync(~0u, l, o);
            p += __shfl_xor_sync(~0u, p, o);
        }
        if ((tid & 31) == 0) { rls[tid >> 5] = l; rpcs[tid >> 5] = p; }
    }
    __syncthreads();
    if (tid == 0) {
        g_pls[bid] = rls[0] + rls[1];
        g_ppc[bid] = rpcs[0] + rpcs[1];
        __threadfence();
        lastS = atomicAdd(&g_ticket, 1u);
    }
    __syncthreads();
    if (lastS == GRID - 1) {                 // last block finalizes
        __threadfence();
        if (tid < GRID) {
            float v = g_pls[tid]; int p = g_ppc[tid];
#pragma unroll
            for (int o = 16; o; o >>= 1) {
                v += __shfl_xor_sync(~0u, v, o);
                p += __shfl_xor_sync(~0u, p, o);
            }
            if ((tid & 31) == 0) { rls[tid >> 5] = v; rpcs[tid >> 5] = p; }
        }
        __syncthreads();
        if (tid == 0) {
            float fs = rls[0] + rls[1] + rls[2] + rls[3];
            int   fc = rpcs[0] + rpcs[1] + rpcs[2] + rpcs[3];
            out[0] = fs / (float)N;
            out[1] = (float)fc / (float)N;
            out[2] = ((float)g_ps / FIXP) / (float)g_pc;
            out[3] = ((float)g_ns / FIXP) / (float)g_nc;
            // reset ALL cross-launch state for graph replay
            for (int k = 0; k < 10; k++) g_cnt[k] = 0;
            g_ps = 0ull; g_ns = 0ull; g_pc = 0u; g_nc = 0u;
            g_ticket = 0u;
            g_bar = 0u;
        }
    }
}

// ---------------------------------------------------------------------------
extern "C" void kernel_launch(void* const* d_in, const int* in_sizes, int n_in,
                              void* d_out, int out_size) {
    const float* x   = (const float*)d_in[0];
    const int*   t32 = (const int*)d_in[1];
    float*       out = (float*)d_out;
    fused_kernel<<<GRID, THREADS>>>(x, t32, out);
}

// round 14
// speedup vs baseline: 3.1777x; 1.0022x over previous
#include <cuda_runtime.h>
#include <math.h>

#define N       8192
#define FIXP    4194304.0f      // 2^22 fixed point for last-row stats
#define GRID    128             // all blocks resident (<=148 SMs) -> spin barrier safe
#define THREADS 640             // 64 rows x 10 labels in query phase
#define QROWS   64
#define LMAX    1024            // per-label bucket capacity (L ~ 820 +- 28)
#define NSTEP   11              // binary search steps: ranges <= 1024

// ---- float-float (Dekker two-sum) helpers ---------------------------------
struct ff { float h, l; };
__device__ __forceinline__ ff ff_add_f(ff x, float a) {
    float s  = x.h + a;
    float bv = s - x.h;
    float e  = (x.h - (s - bv)) + (a - bv);
    float l2 = x.l + e;
    float t  = s + l2;
    ff r; r.h = t; r.l = l2 - (t - s); return r;
}
__device__ __forceinline__ ff ff_add_ff(ff x, ff y) {
    float s  = x.h + y.h;
    float bv = s - x.h;
    float e  = (x.h - (s - bv)) + (y.h - bv) + x.l + y.l;
    float t  = s + e;
    ff r; r.h = t; r.l = e - (t - s); return r;
}

// ---- device globals -------------------------------------------------------
__device__ float              g_x[N];
__device__ unsigned char      g_lab[N];
__device__ float              g_A[N], g_B[N];    // expf(+-16x), original order
__device__ unsigned long long g_tmp[10 * LMAX];  // per-label unordered keys
__device__ int                g_cnt[10];
__device__ float              g_xs[N];           // sorted by (label, x, idx)
__device__ float              g_As[N], g_Bs[N];
__device__ float2             g_PA[N + 16];      // per-label EXCLUSIVE ff prefix of A
__device__ float2             g_SB[N + 16];      // per-label ff SUFFIX sums of B
__device__ float              g_pls[GRID];
__device__ int                g_ppc[GRID];
__device__ unsigned long long g_ps = 0ull, g_ns = 0ull;
__device__ unsigned g_pc = 0u, g_nc = 0u;
__device__ unsigned g_ticket = 0u;
__device__ unsigned g_bar = 0u;                  // grid barrier counter

__device__ __forceinline__ unsigned fenc(float f) {    // order-preserving key
    unsigned u = __float_as_uint(f);
    return (u & 0x80000000u) ? ~u : (u | 0x80000000u);
}
__device__ __forceinline__ float fdec(unsigned k) {
    return __uint_as_float((k & 0x80000000u) ? (k & 0x7FFFFFFFu) : ~k);
}

// All GRID blocks resident -> spin is deadlock-free. Arrive: release-fence +
// atomicAdd. Poll: volatile load (no atomic-serialization) + nanosleep backoff.
__device__ __forceinline__ void grid_barrier(unsigned target) {
    __syncthreads();
    if (threadIdx.x == 0) {
        __threadfence();
        atomicAdd(&g_bar, 1u);
        while (*(volatile unsigned*)&g_bar < target) __nanosleep(64);
        __threadfence();
    }
    __syncthreads();
}

// ---------------------------------------------------------------------------
// Fused kernel: prep -> rank -> build -> query, one launch, 3 grid barriers
// ---------------------------------------------------------------------------
__global__ void __launch_bounds__(THREADS, 1)
fused_kernel(const float* __restrict__ x, const int* __restrict__ t32,
             float* __restrict__ out) {
    __shared__ __align__(16) unsigned char s_buf[32768];  // keys / scan stage / sxs
    __shared__ int   s_off[11], s_scnt[10];
    __shared__ float s_cand[QROWS][10];
    __shared__ float s_v[QROWS][10];
    __shared__ float s_loss[QROWS];
    __shared__ float rls[4]; __shared__ int rpcs[4];
    __shared__ unsigned lastS;
    __shared__ int s_flag;
    const int tid = threadIdx.x;
    const int bid = blockIdx.x;

    // ===== phase 1: prep (block owns elements [64*bid, 64*bid+64) == its query rows)
    if (tid == 0) s_flag = 0;
    __syncthreads();
    // dtype-layout detect: JAX demotes int64->int32; odd int32 words of the
    // first 16KB are zero iff buffer is true int64. 32 distinct words/block.
    if (tid < 32) {
        int k = (bid * 32 + tid) & 2047;
        if (t32[2 * k + 1] != 0) atomicOr(&s_flag, 1);
    }
    __syncthreads();
    const int is32 = s_flag;

    if (tid < 64) {
        const int i = bid * 64 + tid;
        const float xi = x[i];
        const int lbl = is32 ? t32[i] : t32[2 * i];      // int64 LE lo word
        g_x[i] = xi;
        g_lab[i] = (unsigned char)lbl;
        g_A[i] = expf(16.0f * xi);
        g_B[i] = expf(-16.0f * xi);
        const int slot = atomicAdd(&g_cnt[lbl], 1);
        g_tmp[lbl * LMAX + slot] =
            ((unsigned long long)fenc(xi) << 13) | (unsigned)i;  // idx tiebreak

        // last-row stats, fixed point (deterministic across order)
        const float xl = x[N - 1];
        const int   ll = is32 ? t32[N - 1] : t32[2 * (N - 1)];
        float d = fabsf(xl - xi);
        unsigned long long pq = 0ull, nq = 0ull; int pc = 0, nc = 0;
        if (lbl == ll) { if (d < 1.0f) { pq = (unsigned long long)(d * FIXP + 0.5f); pc = 1; } }
        else           { nq = (unsigned long long)(d * FIXP + 0.5f); nc = 1; }
#pragma unroll
        for (int o = 16; o; o >>= 1) {
            pq += __shfl_xor_sync(~0u, pq, o); nq += __shfl_xor_sync(~0u, nq, o);
            pc += __shfl_xor_sync(~0u, pc, o); nc += __shfl_xor_sync(~0u, nc, o);
        }
        if ((tid & 31) == 0) {
            atomicAdd(&g_ps, pq); atomicAdd(&g_ns, nq);
            atomicAdd(&g_pc, (unsigned)pc); atomicAdd(&g_nc, (unsigned)nc);
        }
    }
    grid_barrier(GRID);

    if (tid == 0) {
        int acc = 0;
        for (int c = 0; c < 10; c++) { s_off[c] = acc; int cc = g_cnt[c]; s_scnt[c] = cc; acc += cc; }
        s_off[10] = acc;
    }
    __syncthreads();

    // ===== phase 2: per-label counting rank. 110 tasks (10 labels x 11 chunks
    // of 100 rows; 5 rows/warp) -> at most ONE task per block (no imbalance).
    if (bid < 110) {
        unsigned long long* sk = (unsigned long long*)s_buf;   // 8KB
        const int c = bid % 10, chunk = bid / 10;
        const int L = s_scnt[c], base = s_off[c];
        for (int k = tid; k < LMAX; k += THREADS)
            sk[k] = (k < L) ? g_tmp[c * LMAX + k] : ~0ull;
        __syncthreads();
        const int warp = tid >> 5, lane = tid & 31;
        const int r0 = chunk * 100 + warp * 5;
        if (r0 < L) {
            unsigned long long kr[5]; int cnt[5];
#pragma unroll
            for (int r = 0; r < 5; r++) {
                kr[r] = (r0 + r < L) ? sk[r0 + r] : ~0ull;
                cnt[r] = 0;
            }
#pragma unroll 4
            for (int j = lane; j < LMAX; j += 32) {
                const unsigned long long kj = sk[j];
#pragma unroll
                for (int r = 0; r < 5; r++) cnt[r] += (kj < kr[r]) ? 1 : 0;
            }
#pragma unroll
            for (int r = 0; r < 5; r++)
#pragma unroll
                for (int o = 16; o; o >>= 1)
                    cnt[r] += __shfl_xor_sync(0xffffffffu, cnt[r], o);
            if (lane < 5 && r0 + lane < L) {
                int gr = 0;
#pragma unroll
                for (int r = 0; r < 5; r++) if (lane == r) gr = cnt[r];
                const unsigned long long key = sk[r0 + lane];
                const float xv = fdec((unsigned)(key >> 13));
                g_xs[base + gr] = xv;
                g_As[base + gr] = expf(16.0f * xv);
                g_Bs[base + gr] = expf(-16.0f * xv);
            }
        }
    }
    grid_barrier(2 * GRID);

    // ===== phase 3: ff prefix/suffix scans, block c < 10 handles label c
    if (bid < 10) {
        const int c = bid;
        float* sA = (float*)s_buf;
        float* sB = sA + LMAX;
        const int off = s_off[c], L = s_scnt[c];
        const int base = off + c;           // per-label extra slot
        for (int k = tid; k < L; k += THREADS) { sA[k] = g_As[off + k]; sB[k] = g_Bs[off + k]; }
        __syncthreads();
        const int w = tid >> 5, lane = tid & 31;
        const int chunk = (L + 31) >> 5;
        int st = lane * chunk; if (st > L) st = L;
        int en = st + chunk;   if (en > L) en = L;
        if (w == 0) {
            ff s = {0.f, 0.f};
            for (int k = st; k < en; k++) s = ff_add_f(s, sA[k]);
            ff t = s;
#pragma unroll
            for (int o = 1; o < 32; o <<= 1) {
                ff v; v.h = __shfl_up_sync(~0u, t.h, o);
                      v.l = __shfl_up_sync(~0u, t.l, o);
                if (lane >= o) t = ff_add_ff(v, t);
            }
            ff neg; neg.h = -s.h; neg.l = -s.l;
            ff run = ff_add_ff(t, neg);
            for (int k = st; k < en; k++) {
                g_PA[base + k] = make_float2(run.h, run.l);
                run = ff_add_f(run, sA[k]);
            }
            if (lane == 31) g_PA[base + L] = make_float2(run.h, run.l);
        } else if (w == 1) {
            ff s = {0.f, 0.f};
            for (int r = st; r < en; r++) s = ff_add_f(s, sB[L - 1 - r]);
            ff t = s;
#pragma unroll
            for (int o = 1; o < 32; o <<= 1) {
                ff v; v.h = __shfl_up_sync(~0u, t.h, o);
                      v.l = __shfl_up_sync(~0u, t.l, o);
                if (lane >= o) t = ff_add_ff(v, t);
            }
            ff neg; neg.h = -s.h; neg.l = -s.l;
            ff run = ff_add_ff(t, neg);
            for (int r = st; r < en; r++) {
                run = ff_add_f(run, sB[L - 1 - r]);
                g_SB[base + (L - 1 - r)] = make_float2(run.h, run.l);
            }
            if (lane == 0) g_SB[base + L] = make_float2(0.f, 0.f);
        }
    }
    grid_barrier(3 * GRID);

    // ===== phase 4: query. Thread = (row y, label c). Chain-minimized:
    // m / a0 / b0 searched CONCURRENTLY (range-free monotone predicates,
    // proven in R9); post-th window searches skipped in the common cases
    // (bit-identical predicates guarantee equality with searched results).
    float* sxs = (float*)s_buf;             // 32KB sorted xs
    {
        float4* dst = (float4*)sxs;
        const float4* src = (const float4*)g_xs;
        for (int k = tid; k < N / 4; k += THREADS) dst[k] = src[k];
    }
    __syncthreads();

    const int y = tid / 10, c = tid - y * 10;
    const int i = bid * QROWS + y;
    const float xi  = g_x[i];
    const int   lab = g_lab[i];
    const int   off = s_off[c], cnt = s_scnt[c];
    const bool  own = (c == lab);

    // three interleaved searches, depth NSTEP:
    //   m : first k with xs[k] > xi
    //   a0: first k with ((xs[k]<=xi) ? d<1 : true)   == ranged [0,m) first d<1
    //   b0: first k with (xs[k]>xi && !(d<1))         == ranged [m,cnt) first d>=1
    int lo0 = 0, hi0 = cnt;
    int lo1 = 0, hi1 = own ? cnt : 0;
    int lo2 = 0, hi2 = own ? cnt : 0;
    for (int s = 0; s < NSTEP; s++) {
        if (lo0 < hi0) { int mid = (lo0 + hi0) >> 1;
            if (sxs[off + mid] > xi) hi0 = mid; else lo0 = mid + 1; }
        if (lo1 < hi1) { int mid = (lo1 + hi1) >> 1; float xv = sxs[off + mid];
            bool p = (xv <= xi) ? (fabsf(xi - xv) < 1.0f) : true;
            if (p) hi1 = mid; else lo1 = mid + 1; }
        if (lo2 < hi2) { int mid = (lo2 + hi2) >> 1; float xv = sxs[off + mid];
            bool p = (xv > xi) && !(fabsf(xi - xv) < 1.0f);
            if (p) hi2 = mid; else lo2 = mid + 1; }
    }
    const int m = lo0, a0 = lo1, b0 = lo2;

    float cand, dmn = 0.f, dmx = 0.f;
    if (own) {
        cand = fabsf(xi - sxs[off + a0]);            // a0 < m (self d=0)
        if (b0 > m) cand = fmaxf(cand, fabsf(xi - sxs[off + b0 - 1]));
    } else if (cnt > 0) {
        dmn = fabsf(xi - sxs[off]);
        dmx = fabsf(xi - sxs[off + cnt - 1]);
        cand = fmaxf(dmn, dmx);
    } else cand = 0.f;
    s_cand[y][c] = cand;
    __syncthreads();

    float th = s_cand[y][0];
#pragma unroll
    for (int k = 1; k < 10; k++) th = fmaxf(th, s_cand[y][k]);
    const float pm = fminf(1.0f, th);

    int aa, bb;
    if (own) {
        if (th >= 1.0f) { aa = a0; bb = b0; }        // pm==1.0f -> same predicate
        else {
            int lo = 0, hi = m;
            for (int s = 0; s < NSTEP; s++) {
                if (lo < hi) { int mid = (lo + hi) >> 1;
                    if (fabsf(xi - sxs[off + mid]) < pm) hi = mid; else lo = mid + 1; }
            }
            aa = lo;
            lo = m; hi = cnt;
            for (int s = 0; s < NSTEP; s++) {
                if (lo < hi) { int mid = (lo + hi) >> 1;
                    if (fabsf(xi - sxs[off + mid]) < pm) lo = mid + 1; else hi = mid; }
            }
            bb = lo;
        }
    } else {
        // left distances decrease toward m: dmn<th -> all left inside window
        if (dmn < th) aa = 0;
        else {
            int lo = 0, hi = m;
            for (int s = 0; s < NSTEP; s++) {
                if (lo < hi) { int mid = (lo + hi) >> 1;
                    if (fabsf(xi - sxs[off + mid]) < th) hi = mid; else lo = mid + 1; }
            }
            aa = lo;
        }
        if (dmx < th) bb = cnt;
        else {
            int lo = m, hi = cnt;
            for (int s = 0; s < NSTEP; s++) {
                if (lo < hi) { int mid = (lo + hi) >> 1;
                    if (fabsf(xi - sxs[off + mid]) < th) lo = mid + 1; else hi = mid; }
            }
            bb = lo;
        }
    }

    {   // e = Bi*(sum A over [aa,m)) + Ai*(sum B over [m,bb)), ff-compensated
        const float Ai = g_A[i], Bi = g_B[i];
        const int e = off + c;
        float2 Pm = g_PA[e + m],  Paa = g_PA[e + aa];
        float2 Sm = g_SB[e + m],  Sbb = g_SB[e + bb];
        float left  = (Pm.x - Paa.x) + (Pm.y - Paa.y);
        float right = (Sm.x - Sbb.x) + (Sm.y - Sbb.y);
        s_v[y][c] = Bi * left + Ai * right;
    }
    __syncthreads();

    if (c == 0) {
        float pos = s_v[y][lab], neg = 0.f;
#pragma unroll
        for (int k = 0; k < 10; k++) if (k != lab) neg += s_v[y][k];
        float loss = 0.f;
        if (th > 0.f && pos > 0.f)
            loss = logf((pos + fmaxf(neg, 0.f)) / pos);
        s_loss[y] = loss;
    }
    __syncthreads();

    if (tid < QROWS) {                       // 2 warps reduce 64 rows
        float l = s_loss[tid];
        int   p = (l < 0.6f) ? 1 : 0;
#pragma unroll
        for (int o = 16; o; o >>= 1) {
            l += __shfl_xor_sync(~0u, l, o);
            p += __shfl_xor_sync(~0u, p, o);
        }
        if ((tid & 31) == 0) { rls[tid >> 5] = l; rpcs[tid >> 5] = p; }
    }
    __syncthreads();
    if (tid == 0) {
        g_pls[bid] = rls[0] + rls[1];
        g_ppc[bid] = rpcs[0] + rpcs[1];
        __threadfence();
        lastS = atomicAdd(&g_ticket, 1u);
    }
    __syncthreads();
    if (lastS == GRID - 1) {                 // last block finalizes
        __threadfence();
        if (tid < GRID) {
            float v = g_pls[tid]; int p = g_ppc[tid];
#pragma unroll
            for (int o = 16; o; o >>= 1) {
                v += __shfl_xor_sync(~0u, v, o);
                p += __shfl_xor_sync(~0u, p, o);
            }
            if ((tid & 31) == 0) { rls[tid >> 5] = v; rpcs[tid >> 5] = p; }
        }
        __syncthreads();
        if (tid == 0) {
            float fs = rls[0] + rls[1] + rls[2] + rls[3];
            int   fc = rpcs[0] + rpcs[1] + rpcs[2] + rpcs[3];
            out[0] = fs / (float)N;
            out[1] = (float)fc / (float)N;
            out[2] = ((float)g_ps / FIXP) / (float)g_pc;
            out[3] = ((float)g_ns / FIXP) / (float)g_nc;
            // reset ALL cross-launch state for graph replay
            for (int k = 0; k < 10; k++) g_cnt[k] = 0;
            g_ps = 0ull; g_ns = 0ull; g_pc = 0u; g_nc = 0u;
            g_ticket = 0u;
            g_bar = 0u;
        }
    }
}

// ---------------------------------------------------------------------------
extern "C" void kernel_launch(void* const* d_in, const int* in_sizes, int n_in,
                              void* d_out, int out_size) {
    const float* x   = (const float*)d_in[0];
    const int*   t32 = (const int*)d_in[1];
    float*       out = (float*)d_out;
    fused_kernel<<<GRID, THREADS>>>(x, t32, out);
}